// round 1
// baseline (speedup 1.0000x reference)
#include <cuda_runtime.h>
#include <cuda_bf16.h>
#include <math.h>

#define NB   2
#define CIN  200
#define CQ   50
#define LL   16384
#define NSC  4
#define WIN  64
#define KCL  256   // clusters per scale
#define NCHUNK 8   // sort chunks per (n,u)
#define CHSZ 2048

// ---------------- device scratch (no runtime allocation allowed) ----------------
__device__ float g_xembed[(size_t)NB*LL*CQ];        // [n][l][c]  (c stride 50)
__device__ float g_yembed[(size_t)NB*LL*CIN];       // [n][l][o]  (o stride 200)
__device__ float g_att[(size_t)NB*NSC*LL*CIN];      // [n][u][l][oc]
__device__ int   g_perm[NB*NSC*LL];                 // sorted pos -> original l
__device__ int   g_hist[NB*NSC*NCHUNK*32];
__device__ float g_WyT[CIN*CIN];                    // [c][o]
__device__ float g_WoutT[(CIN*NSC)*CIN];            // [k][co]
__device__ float g_WxT[CIN*CQ*9];                   // [c][o][tap]

// ---------------- weight transposes (coalesced reads later) ----------------
__global__ void prep_kernel(const float* __restrict__ Wx,
                            const float* __restrict__ Wy,
                            const float* __restrict__ Wout) {
    int i = blockIdx.x * blockDim.x + threadIdx.x;
    if (i < CIN*CIN) {
        int o = i / CIN, c = i % CIN;
        g_WyT[c*CIN + o] = Wy[i];
    }
    if (i < CIN*(CIN*NSC)) {
        int co = i / (CIN*NSC), kk = i % (CIN*NSC);
        g_WoutT[(size_t)kk*CIN + co] = Wout[i];
    }
    if (i < CQ*CIN*9) {
        int o = i / (CIN*9); int rem = i % (CIN*9);
        int c = rem / 9, tap = rem % 9;
        g_WxT[c*(CQ*9) + o*9 + tap] = Wx[i];
    }
}

// ---------------- conv3x3 reflect, 200 -> 50, output pixel-major ----------------
__global__ __launch_bounds__(256) void conv_kernel(const float* __restrict__ input) {
    int tile = blockIdx.x, n = blockIdx.y;
    int l0 = tile * 64;
    int y = l0 >> 7, x0 = l0 & 127;
    __shared__ float inS[3][66];
    __shared__ float WxS[64*9];     // o in [0,64), zero-padded for o>=50
    int tid = threadIdx.x, tx = tid & 15, ty = tid >> 4;
    for (int e = tid; e < 64*9; e += 256) if (e >= CQ*9) WxS[e] = 0.f;
    float acc[4][4] = {{0.f}};
    const float* inb = input + (size_t)n * CIN * LL;
    for (int c = 0; c < CIN; ++c) {
        __syncthreads();
        for (int e = tid; e < CQ*9; e += 256) WxS[e] = g_WxT[c*(CQ*9) + e];
        for (int e = tid; e < 3*66; e += 256) {
            int rr = e / 66, cc = e % 66;
            int gy = y - 1 + rr; gy = gy < 0 ? 1 : (gy > 127 ? 126 : gy);
            int gx = x0 - 1 + cc; gx = gx < 0 ? 1 : (gx > 127 ? 126 : gx);
            inS[rr][cc] = inb[(size_t)c*LL + (gy << 7) + gx];
        }
        __syncthreads();
        #pragma unroll
        for (int ky = 0; ky < 3; ky++)
        #pragma unroll
        for (int kx = 0; kx < 3; kx++) {
            int tap = ky*3 + kx;
            float wv[4], iv[4];
            #pragma unroll
            for (int b = 0; b < 4; b++) wv[b] = WxS[(tx + 16*b)*9 + tap];
            #pragma unroll
            for (int a = 0; a < 4; a++) iv[a] = inS[ky][(ty + 16*a) + kx];
            #pragma unroll
            for (int a = 0; a < 4; a++)
            #pragma unroll
            for (int b = 0; b < 4; b++) acc[a][b] += iv[a] * wv[b];
        }
    }
    #pragma unroll
    for (int a = 0; a < 4; a++) {
        int l = l0 + ty + 16*a;
        #pragma unroll
        for (int b = 0; b < 4; b++) {
            int o = tx + 16*b;
            if (o < CQ) g_xembed[((size_t)n*LL + l)*CQ + o] = acc[a][b];
        }
    }
}

// ---------------- 1x1 Wy GEMM: y[n][l][o] = sum_c Wy[o][c] in[n][c][l] ----------------
__global__ __launch_bounds__(256) void yembed_kernel(const float* __restrict__ input) {
    int tile = blockIdx.x, n = blockIdx.y;
    int l0 = tile * 64;
    __shared__ float inS[16][64];
    __shared__ float WyS[16][208];
    int tid = threadIdx.x, tx = tid & 15, ty = tid >> 4;
    float acc[4][13] = {{0.f}};
    const float* inb = input + (size_t)n * CIN * LL;
    for (int cb = 0; cb < 208; cb += 16) {
        __syncthreads();
        for (int e = tid; e < 16*64; e += 256) {
            int cc = e >> 6, li = e & 63;
            inS[cc][li] = (cb + cc < CIN) ? inb[(size_t)(cb + cc)*LL + l0 + li] : 0.f;
        }
        for (int e = tid; e < 16*208; e += 256) {
            int cc = e / 208, o = e % 208;
            WyS[cc][o] = (o < CIN && cb + cc < CIN) ? g_WyT[(cb + cc)*CIN + o] : 0.f;
        }
        __syncthreads();
        #pragma unroll
        for (int cc = 0; cc < 16; cc++) {
            float lv[4], wv[13];
            #pragma unroll
            for (int a = 0; a < 4; a++) lv[a] = inS[cc][ty + 16*a];
            #pragma unroll
            for (int b = 0; b < 13; b++) wv[b] = WyS[cc][tx + 16*b];
            #pragma unroll
            for (int a = 0; a < 4; a++)
            #pragma unroll
            for (int b = 0; b < 13; b++) acc[a][b] += lv[a] * wv[b];
        }
    }
    #pragma unroll
    for (int a = 0; a < 4; a++) {
        int l = l0 + ty + 16*a;
        #pragma unroll
        for (int b = 0; b < 13; b++) {
            int o = tx + 16*b;
            if (o < CIN) g_yembed[((size_t)n*LL + l)*CIN + o] = acc[a][b];
        }
    }
}

// ---------------- sort: per-(n,u) histogram ----------------
__global__ void hist_kernel(const int* __restrict__ sem) {
    int chunk = blockIdx.x, u = blockIdx.y, n = blockIdx.z;
    __shared__ int h[32];
    int tid = threadIdx.x;
    if (tid < 32) h[tid] = 0;
    __syncthreads();
    const int* lab = sem + (size_t)(n*NSC + u)*LL + chunk*CHSZ;
    for (int i = tid; i < CHSZ; i += 256) atomicAdd(&h[lab[i] & 31], 1);
    __syncthreads();
    if (tid < 32) g_hist[((n*NSC + u)*NCHUNK + chunk)*32 + tid] = h[tid];
}

// ---------------- sort: scan + stable scatter (warp-per-chunk, lane-per-label) --------
__global__ void scatter_kernel(const int* __restrict__ sem) {
    int u = blockIdx.x, n = blockIdx.y;
    __shared__ int cnt[NCHUNK][32];
    __shared__ int start[NCHUNK][32];
    __shared__ int buf[NCHUNK][128];
    int tid = threadIdx.x;
    cnt[tid >> 5][tid & 31] = g_hist[((n*NSC + u)*NCHUNK + (tid >> 5))*32 + (tid & 31)];
    __syncthreads();
    if (tid < 32) {
        int tot = 0;
        #pragma unroll
        for (int ch = 0; ch < NCHUNK; ch++) tot += cnt[ch][tid];
        int inc = tot;
        #pragma unroll
        for (int off = 1; off < 32; off <<= 1) {
            int v = __shfl_up_sync(0xffffffffu, inc, off);
            if (tid >= off) inc += v;
        }
        int run = inc - tot;   // exclusive prefix over labels
        #pragma unroll
        for (int ch = 0; ch < NCHUNK; ch++) { start[ch][tid] = run; run += cnt[ch][tid]; }
    }
    __syncthreads();
    int w = tid >> 5, lane = tid & 31;
    int off = start[w][lane];
    const int* lab = sem + (size_t)(n*NSC + u)*LL + w*CHSZ;
    int* pout = g_perm + (n*NSC + u)*LL;
    for (int t0 = 0; t0 < CHSZ; t0 += 128) {
        #pragma unroll
        for (int j = 0; j < 4; j++) buf[w][lane*4 + j] = lab[t0 + lane*4 + j];
        __syncwarp();
        #pragma unroll 8
        for (int e = 0; e < 128; e++) {
            if (buf[w][e] == lane) { pout[off] = w*CHSZ + t0 + e; off++; }
        }
        __syncwarp();
    }
}

// ---------------- attention per cluster: S = Q K_n^T, softmax, O = P V ----------------
// dyn smem layout: P[64][193] | Qs[64][53] (aliased by V[16][208]) | Ks[192][53]
__global__ __launch_bounds__(256) void attn_kernel() {
    extern __shared__ float sm[];
    float* P  = sm;
    float* Qs = sm + 64*193;
    float* Ks = Qs + 64*53;
    float* Vs = Qs;                     // alias: 16*208=3328 <= 64*53=3392
    __shared__ int lperm[192];
    int k = blockIdx.x, u = blockIdx.y, n = blockIdx.z;
    int tid = threadIdx.x, tx = tid & 15, ty = tid >> 4;

    const int* pbase = g_perm + (n*NSC + u)*LL;
    if (tid < 192) {
        int jj = tid & 63;
        int kk = tid < 64 ? k : (tid < 128 ? (k + KCL - 1) & (KCL - 1) : (k + 1) & (KCL - 1));
        lperm[tid] = pbase[kk*WIN + jj];
    }
    __syncthreads();

    const float* xb = g_xembed + (size_t)n*LL*CQ;
    for (int e = tid; e < 192*CQ; e += 256) {
        int j = e / CQ, c = e % CQ;
        Ks[j*53 + c] = xb[(size_t)lperm[j]*CQ + c];
    }
    __syncthreads();
    for (int e = tid; e < 64*CQ; e += 256) {
        int i = e / CQ, c = e % CQ;
        Qs[i*53 + c] = Ks[i*53 + c];     // Q is the raw (unnormalized) self cluster
    }
    __syncthreads();
    if (tid < 192) {                      // normalize keys: x / max(||x||, eps)
        float ss = 0.f;
        #pragma unroll 10
        for (int c = 0; c < CQ; c++) { float v = Ks[tid*53 + c]; ss += v*v; }
        float s = 1.f / fmaxf(sqrtf(ss), 5e-5f);
        #pragma unroll 10
        for (int c = 0; c < CQ; c++) Ks[tid*53 + c] *= s;
    }
    __syncthreads();

    // S = Q @ K^T  (64 x 192, K=50)
    {
        float accS[4][12] = {{0.f}};
        #pragma unroll 5
        for (int c = 0; c < CQ; c++) {
            float qv[4], kv[12];
            #pragma unroll
            for (int a = 0; a < 4; a++) qv[a] = Qs[(ty + 16*a)*53 + c];
            #pragma unroll
            for (int b = 0; b < 12; b++) kv[b] = Ks[(tx + 16*b)*53 + c];
            #pragma unroll
            for (int a = 0; a < 4; a++)
            #pragma unroll
            for (int b = 0; b < 12; b++) accS[a][b] += qv[a] * kv[b];
        }
        #pragma unroll
        for (int a = 0; a < 4; a++)
        #pragma unroll
        for (int b = 0; b < 12; b++)
            P[(ty + 16*a)*193 + tx + 16*b] = accS[a][b];
    }
    __syncthreads();

    // softmax over 192 cols: 4 consecutive lanes per row
    {
        int r = tid >> 2, q = tid & 3;
        float* prow = P + r*193 + q*48;
        float mx = -1e30f;
        #pragma unroll 8
        for (int m = 0; m < 48; m++) mx = fmaxf(mx, prow[m]);
        mx = fmaxf(mx, __shfl_xor_sync(0xffffffffu, mx, 1));
        mx = fmaxf(mx, __shfl_xor_sync(0xffffffffu, mx, 2));
        float sum = 0.f;
        #pragma unroll 8
        for (int m = 0; m < 48; m++) { float e = __expf(prow[m] - mx); prow[m] = e; sum += e; }
        sum += __shfl_xor_sync(0xffffffffu, sum, 1);
        sum += __shfl_xor_sync(0xffffffffu, sum, 2);
        float inv = 1.f / sum;
        #pragma unroll 8
        for (int m = 0; m < 48; m++) prow[m] *= inv;
    }
    __syncthreads();

    // O = P @ V  (64 x 200, K=192), V staged in 16-row chunks
    float accO[4][13] = {{0.f}};
    const float* yb = g_yembed + (size_t)n*LL*CIN;
    for (int j0 = 0; j0 < 192; j0 += 16) {
        __syncthreads();
        for (int e = tid; e < 16*208; e += 256) {
            int jj = e / 208, c = e % 208;
            Vs[jj*208 + c] = (c < CIN) ? yb[(size_t)lperm[j0 + jj]*CIN + c] : 0.f;
        }
        __syncthreads();
        #pragma unroll
        for (int jj = 0; jj < 16; jj++) {
            float pv[4], vv[13];
            #pragma unroll
            for (int a = 0; a < 4; a++) pv[a] = P[(ty + 16*a)*193 + j0 + jj];
            #pragma unroll
            for (int b = 0; b < 13; b++) vv[b] = Vs[jj*208 + tx + 16*b];
            #pragma unroll
            for (int a = 0; a < 4; a++)
            #pragma unroll
            for (int b = 0; b < 13; b++) accO[a][b] += pv[a] * vv[b];
        }
    }
    float* ob = g_att + (size_t)(n*NSC + u)*LL*CIN;
    #pragma unroll
    for (int a = 0; a < 4; a++) {
        int i = ty + 16*a;
        size_t rb = (size_t)lperm[i]*CIN;
        #pragma unroll
        for (int b = 0; b < 13; b++) {
            int c = tx + 16*b;
            if (c < CIN) ob[rb + c] = accO[a][b];
        }
    }
}

// ---------------- Wout 1x1 (K=800) + bias + residual ----------------
__global__ __launch_bounds__(256) void out_kernel(const float* __restrict__ input,
                                                  const float* __restrict__ bout,
                                                  float* __restrict__ out) {
    int tile = blockIdx.x, n = blockIdx.y;
    int l0 = tile * 64;
    __shared__ float attS[16*65];
    __shared__ float WoS[16][208];
    int tid = threadIdx.x, tx = tid & 15, ty = tid >> 4;
    float acc[13][4] = {{0.f}};
    for (int k0 = 0; k0 < CIN*NSC; k0 += 16) {
        __syncthreads();
        for (int e = tid; e < 16*64; e += 256) {
            int li = e >> 4, kc = e & 15;
            int kk = k0 + kc;
            int u = kk / CIN, oc = kk % CIN;
            attS[kc*65 + li] = g_att[((size_t)(n*NSC + u)*LL + l0 + li)*CIN + oc];
        }
        for (int e = tid; e < 16*208; e += 256) {
            int kc = e / 208, co = e % 208;
            WoS[kc][co] = (co < CIN) ? g_WoutT[(size_t)(k0 + kc)*CIN + co] : 0.f;
        }
        __syncthreads();
        #pragma unroll
        for (int kc = 0; kc < 16; kc++) {
            float av[4], wv[13];
            #pragma unroll
            for (int b = 0; b < 4; b++) av[b] = attS[kc*65 + tx + 16*b];
            #pragma unroll
            for (int a = 0; a < 13; a++) wv[a] = WoS[kc][ty + 16*a];
            #pragma unroll
            for (int a = 0; a < 13; a++)
            #pragma unroll
            for (int b = 0; b < 4; b++) acc[a][b] += wv[a] * av[b];
        }
    }
    #pragma unroll
    for (int a = 0; a < 13; a++) {
        int co = ty + 16*a;
        if (co < CIN) {
            float bo = bout[co];
            #pragma unroll
            for (int b = 0; b < 4; b++) {
                int l = l0 + tx + 16*b;
                size_t idx = ((size_t)n*CIN + co)*LL + l;
                out[idx] = acc[a][b] + bo + input[idx];
            }
        }
    }
}

// ---------------- launch ----------------
extern "C" void kernel_launch(void* const* d_in, const int* in_sizes, int n_in,
                              void* d_out, int out_size) {
    const float* input = (const float*)d_in[0];
    const int*   sem   = (const int*)d_in[1];
    const float* Wx    = (const float*)d_in[2];
    const float* Wy    = (const float*)d_in[3];
    const float* Wout  = (const float*)d_in[4];
    const float* bout  = (const float*)d_in[5];
    float* out = (float*)d_out;

    cudaFuncSetAttribute(attn_kernel, cudaFuncAttributeMaxDynamicSharedMemorySize, 103680);

    prep_kernel<<<640, 256>>>(Wx, Wy, Wout);
    conv_kernel<<<dim3(LL/64, NB), 256>>>(input);
    yembed_kernel<<<dim3(LL/64, NB), 256>>>(input);
    hist_kernel<<<dim3(NCHUNK, NSC, NB), 256>>>(sem);
    scatter_kernel<<<dim3(NSC, NB), 256>>>(sem);
    attn_kernel<<<dim3(KCL, NSC, NB), 256, 103680>>>();
    out_kernel<<<dim3(LL/64, NB), 256>>>(input, bout, out);
}

// round 3
// speedup vs baseline: 1.2316x; 1.2316x over previous
#include <cuda_runtime.h>
#include <cuda_bf16.h>
#include <math.h>

#define NB   2
#define CIN  200
#define CQ   50
#define LL   16384
#define NSC  4
#define WIN  64
#define KCL  256
#define NCHUNK 8
#define CHSZ 2048

typedef unsigned long long ull;

#define FMA2(acc, a, b) asm("fma.rn.f32x2 %0, %1, %2, %0;" : "+l"(acc) : "l"(a), "l"(b))

__device__ __forceinline__ ull dup2f(float x) {
    ull r; asm("mov.b64 %0, {%1, %1};" : "=l"(r) : "f"(x)); return r;
}
__device__ __forceinline__ float2 upk2(ull v) {
    float2 f; asm("mov.b64 {%0, %1}, %2;" : "=f"(f.x), "=f"(f.y) : "l"(v)); return f;
}
__device__ __forceinline__ ull ldp(const float* p) {
    return *reinterpret_cast<const ull*>(p);
}

// ---------------- device scratch ----------------
__device__ float g_xembed[(size_t)NB*LL*CQ];        // [n][l][c]
__device__ float g_yembed[(size_t)NB*LL*CIN];       // [n][l][o]
__device__ float g_att[(size_t)NB*NSC*LL*CIN];      // [n][u][l][oc]
__device__ int   g_perm[NB*NSC*LL];
__device__ int   g_hist[NB*NSC*NCHUNK*32];
__device__ float g_WyT[CIN*CIN];                    // [c][o]
__device__ float g_WoutT[(CIN*NSC)*CIN];            // [k][co]
__device__ float g_WxT[CIN*9*64];                   // [c][tap][o(64, zero-pad)]

// ---------------- weight transposes ----------------
__global__ void prep_kernel(const float* __restrict__ Wx,
                            const float* __restrict__ Wy,
                            const float* __restrict__ Wout) {
    for (int i = blockIdx.x * blockDim.x + threadIdx.x; i < CIN*CIN*NSC;
         i += gridDim.x * blockDim.x) {
        if (i < CIN*CIN) {
            int o = i / CIN, c = i % CIN;
            g_WyT[c*CIN + o] = Wy[i];
        }
        {
            int co = i / (CIN*NSC), kk = i % (CIN*NSC);
            g_WoutT[(size_t)kk*CIN + co] = Wout[i];
        }
        if (i < CIN*9*64) {
            int c = i / 576, r = i % 576;
            int tap = r >> 6, o = r & 63;
            g_WxT[i] = (o < CQ) ? Wx[((size_t)o*CIN + c)*9 + tap] : 0.f;
        }
    }
}

// ---------------- conv3x3 reflect, 200->50, FFMA2 ----------------
__global__ __launch_bounds__(256) void conv_kernel(const float* __restrict__ input) {
    int tile = blockIdx.x, n = blockIdx.y;
    int l0 = tile * 64;
    int y = l0 >> 7, x0 = l0 & 127;
    __shared__ float inS[3][66];
    __shared__ float WxS[576];
    int tid = threadIdx.x, tx = tid & 15, ty = tid >> 4;
    ull acc2[4][2] = {{0ull,0ull},{0ull,0ull},{0ull,0ull},{0ull,0ull}};
    const float* inb = input + (size_t)n * CIN * LL;
    for (int c = 0; c < CIN; ++c) {
        __syncthreads();
        for (int e = tid; e < 576; e += 256) WxS[e] = g_WxT[c*576 + e];
        if (tid < 198) {
            int rr = tid / 66, cc = tid % 66;
            int gy = y - 1 + rr; gy = gy < 0 ? 1 : (gy > 127 ? 126 : gy);
            int gx = x0 - 1 + cc; gx = gx < 0 ? 1 : (gx > 127 ? 126 : gx);
            inS[rr][cc] = inb[(size_t)c*LL + (gy << 7) + gx];
        }
        __syncthreads();
        #pragma unroll
        for (int ky = 0; ky < 3; ky++)
        #pragma unroll
        for (int kx = 0; kx < 3; kx++) {
            int tap = ky*3 + kx;
            ull w0 = ldp(&WxS[tap*64 + 2*tx]);
            ull w1 = ldp(&WxS[tap*64 + 2*tx + 32]);
            #pragma unroll
            for (int a = 0; a < 4; a++) {
                ull iv = dup2f(inS[ky][(ty + 16*a) + kx]);
                FMA2(acc2[a][0], iv, w0);
                FMA2(acc2[a][1], iv, w1);
            }
        }
    }
    #pragma unroll
    for (int a = 0; a < 4; a++) {
        int l = l0 + ty + 16*a;
        #pragma unroll
        for (int p = 0; p < 2; p++) {
            int o = 2*tx + 32*p;
            if (o + 1 < CQ)
                *reinterpret_cast<float2*>(&g_xembed[((size_t)n*LL + l)*CQ + o]) = upk2(acc2[a][p]);
        }
    }
}

// ---------------- 1x1 Wy GEMM, FFMA2 ----------------
__global__ __launch_bounds__(256) void yembed_kernel(const float* __restrict__ input) {
    int tile = blockIdx.x, n = blockIdx.y;
    int l0 = tile * 64;
    __shared__ float inS[16*64];
    __shared__ float WyS[16*208];
    int tid = threadIdx.x, tx = tid & 31, ty8 = tid >> 5;
    ull acc2[13][2];
    #pragma unroll
    for (int pa = 0; pa < 13; pa++) { acc2[pa][0] = 0ull; acc2[pa][1] = 0ull; }
    const float* inb = input + (size_t)n * CIN * LL;
    for (int cb = 0; cb < 208; cb += 16) {
        __syncthreads();
        for (int e = tid; e < 16*64; e += 256) {
            int cc = e >> 6, li = e & 63;
            inS[e] = (cb + cc < CIN) ? inb[(size_t)(cb + cc)*LL + l0 + li] : 0.f;
        }
        for (int e = tid; e < 16*208; e += 256) {
            int cc = e / 208, o = e % 208;
            WyS[e] = (o < CIN && cb + cc < CIN) ? g_WyT[(cb + cc)*CIN + o] : 0.f;
        }
        __syncthreads();
        #pragma unroll
        for (int cc = 0; cc < 16; cc++) {
            ull d0 = dup2f(inS[cc*64 + tx]);
            ull d1 = dup2f(inS[cc*64 + tx + 32]);
            #pragma unroll
            for (int pa = 0; pa < 13; pa++) {
                ull wp = ldp(&WyS[cc*208 + 2*ty8 + 16*pa]);
                FMA2(acc2[pa][0], d0, wp);
                FMA2(acc2[pa][1], d1, wp);
            }
        }
    }
    #pragma unroll
    for (int pa = 0; pa < 13; pa++) {
        int o = 2*ty8 + 16*pa;
        if (o + 1 < CIN) {
            *reinterpret_cast<float2*>(&g_yembed[((size_t)n*LL + l0 + tx)*CIN + o]) = upk2(acc2[pa][0]);
            *reinterpret_cast<float2*>(&g_yembed[((size_t)n*LL + l0 + tx + 32)*CIN + o]) = upk2(acc2[pa][1]);
        }
    }
}

// ---------------- sort: histogram ----------------
__global__ void hist_kernel(const int* __restrict__ sem) {
    int chunk = blockIdx.x, u = blockIdx.y, n = blockIdx.z;
    __shared__ int h[32];
    int tid = threadIdx.x;
    if (tid < 32) h[tid] = 0;
    __syncthreads();
    const int* lab = sem + (size_t)(n*NSC + u)*LL + chunk*CHSZ;
    for (int i = tid; i < CHSZ; i += 256) atomicAdd(&h[lab[i] & 31], 1);
    __syncthreads();
    if (tid < 32) g_hist[((n*NSC + u)*NCHUNK + chunk)*32 + tid] = h[tid];
}

// ---------------- sort: scan + stable scatter ----------------
__global__ void scatter_kernel(const int* __restrict__ sem) {
    int u = blockIdx.x, n = blockIdx.y;
    __shared__ int cnt[NCHUNK][32];
    __shared__ int start[NCHUNK][32];
    __shared__ int buf[NCHUNK][128];
    int tid = threadIdx.x;
    cnt[tid >> 5][tid & 31] = g_hist[((n*NSC + u)*NCHUNK + (tid >> 5))*32 + (tid & 31)];
    __syncthreads();
    if (tid < 32) {
        int tot = 0;
        #pragma unroll
        for (int ch = 0; ch < NCHUNK; ch++) tot += cnt[ch][tid];
        int inc = tot;
        #pragma unroll
        for (int off = 1; off < 32; off <<= 1) {
            int v = __shfl_up_sync(0xffffffffu, inc, off);
            if (tid >= off) inc += v;
        }
        int run = inc - tot;
        #pragma unroll
        for (int ch = 0; ch < NCHUNK; ch++) { start[ch][tid] = run; run += cnt[ch][tid]; }
    }
    __syncthreads();
    int w = tid >> 5, lane = tid & 31;
    int off = start[w][lane];
    const int* lab = sem + (size_t)(n*NSC + u)*LL + w*CHSZ;
    int* pout = g_perm + (n*NSC + u)*LL;
    for (int t0 = 0; t0 < CHSZ; t0 += 128) {
        #pragma unroll
        for (int j = 0; j < 4; j++) buf[w][lane*4 + j] = lab[t0 + lane*4 + j];
        __syncwarp();
        #pragma unroll 8
        for (int e = 0; e < 128; e++) {
            if (buf[w][e] == lane) { pout[off] = w*CHSZ + t0 + e; off++; }
        }
        __syncwarp();
    }
}

// ---------------- attention: S = Q K_n^T, softmax, O = P V, FFMA2 ----------------
// dyn smem: P[64][194] | region2 = max(KsT[50][194]+Qs[64][52], Vs[64][208])
__global__ __launch_bounds__(256) void attn_kernel() {
    extern __shared__ float sm[];
    float* P   = sm;                  // 64*194 = 12416
    float* Vs  = sm + 64*194;         // 64*208 = 13312
    float* KsT = Vs;                  // 50*194 = 9700
    float* Qs  = KsT + 50*194;        // 64*52  = 3328
    __shared__ int lperm[192];
    int k = blockIdx.x, u = blockIdx.y, n = blockIdx.z;
    int tid = threadIdx.x, tx = tid & 7, ty = tid >> 3;
    int r0 = ty, r1 = ty + 32;

    const int* pbase = g_perm + (n*NSC + u)*LL;
    if (tid < 192) {
        int jj = tid & 63;
        int kk = tid < 64 ? k : (tid < 128 ? (k + KCL - 1) & (KCL - 1) : (k + 1) & (KCL - 1));
        lperm[tid] = pbase[kk*WIN + jj];
    }
    __syncthreads();

    const float* xb = g_xembed + (size_t)n*LL*CQ;
    for (int e = tid; e < 192*CQ; e += 256) {
        int j = e / CQ, c = e - j*CQ;
        KsT[c*194 + j] = xb[(size_t)lperm[j]*CQ + c];
    }
    for (int e = tid; e < 64*25; e += 256) {
        int i = e / 25, c2 = e - i*25;
        *reinterpret_cast<float2*>(&Qs[i*52 + 2*c2]) =
            *reinterpret_cast<const float2*>(&xb[(size_t)lperm[i]*CQ + 2*c2]);
    }
    __syncthreads();
    if (tid < 192) {
        float ss = 0.f;
        #pragma unroll 10
        for (int c = 0; c < CQ; c++) { float v = KsT[c*194 + tid]; ss += v*v; }
        float s = 1.f / fmaxf(sqrtf(ss), 5e-5f);
        #pragma unroll 10
        for (int c = 0; c < CQ; c++) KsT[c*194 + tid] *= s;
    }
    __syncthreads();

    // S = Q @ K^T
    {
        ull accS[2][12];
        #pragma unroll
        for (int pr = 0; pr < 12; pr++) { accS[0][pr] = 0ull; accS[1][pr] = 0ull; }
        #pragma unroll 5
        for (int c = 0; c < CQ; c++) {
            ull d0 = dup2f(Qs[r0*52 + c]);
            ull d1 = dup2f(Qs[r1*52 + c]);
            #pragma unroll
            for (int pr = 0; pr < 12; pr++) {
                ull kp = ldp(&KsT[c*194 + 2*tx + 16*pr]);
                FMA2(accS[0][pr], d0, kp);
                FMA2(accS[1][pr], d1, kp);
            }
        }
        #pragma unroll
        for (int pr = 0; pr < 12; pr++) {
            int col = 2*tx + 16*pr;
            *reinterpret_cast<float2*>(&P[r0*194 + col]) = upk2(accS[0][pr]);
            *reinterpret_cast<float2*>(&P[r1*194 + col]) = upk2(accS[1][pr]);
        }
    }
    __syncthreads();

    // softmax over 192 cols
    {
        int r = tid >> 2, q = tid & 3;
        float* prow = P + r*194 + q*48;
        float mx = -1e30f;
        #pragma unroll 8
        for (int m = 0; m < 48; m++) mx = fmaxf(mx, prow[m]);
        mx = fmaxf(mx, __shfl_xor_sync(0xffffffffu, mx, 1));
        mx = fmaxf(mx, __shfl_xor_sync(0xffffffffu, mx, 2));
        float sum = 0.f;
        #pragma unroll 8
        for (int m = 0; m < 48; m++) { float e = __expf(prow[m] - mx); prow[m] = e; sum += e; }
        sum += __shfl_xor_sync(0xffffffffu, sum, 1);
        sum += __shfl_xor_sync(0xffffffffu, sum, 2);
        float inv = 1.f / sum;
        #pragma unroll 8
        for (int m = 0; m < 48; m++) prow[m] *= inv;
    }
    __syncthreads();
    // zero V pad cols (200..207) once
    for (int e = tid; e < 64*8; e += 256) {
        int jj = e >> 3, cc = 200 + (e & 7);
        Vs[jj*208 + cc] = 0.f;
    }

    // O = P @ V, V staged in 64-row chunks
    ull accO[2][13];
    #pragma unroll
    for (int pr = 0; pr < 13; pr++) { accO[0][pr] = 0ull; accO[1][pr] = 0ull; }
    const float* yb = g_yembed + (size_t)n*LL*CIN;
    for (int ch = 0; ch < 3; ch++) {
        __syncthreads();
        for (int e = tid; e < 64*50; e += 256) {
            int jj = e / 50, c4 = e - jj*50;
            *reinterpret_cast<float4*>(&Vs[jj*208 + 4*c4]) =
                *reinterpret_cast<const float4*>(&yb[(size_t)lperm[ch*64 + jj]*CIN + 4*c4]);
        }
        __syncthreads();
        #pragma unroll 4
        for (int jj = 0; jj < 64; jj++) {
            ull d0 = dup2f(P[r0*194 + ch*64 + jj]);
            ull d1 = dup2f(P[r1*194 + ch*64 + jj]);
            #pragma unroll
            for (int pr = 0; pr < 13; pr++) {
                ull vp = ldp(&Vs[jj*208 + 2*tx + 16*pr]);
                FMA2(accO[0][pr], d0, vp);
                FMA2(accO[1][pr], d1, vp);
            }
        }
    }
    float* ob = g_att + (size_t)(n*NSC + u)*LL*CIN;
    size_t rb0 = (size_t)lperm[r0]*CIN;
    size_t rb1 = (size_t)lperm[r1]*CIN;
    #pragma unroll
    for (int pr = 0; pr < 13; pr++) {
        int c = 2*tx + 16*pr;
        if (c + 1 < CIN) {
            *reinterpret_cast<float2*>(&ob[rb0 + c]) = upk2(accO[0][pr]);
            *reinterpret_cast<float2*>(&ob[rb1 + c]) = upk2(accO[1][pr]);
        }
    }
}

// ---------------- Wout 1x1 (K=800) + bias + residual, FFMA2 ----------------
__global__ __launch_bounds__(256) void out_kernel(const float* __restrict__ input,
                                                  const float* __restrict__ bout,
                                                  float* __restrict__ out) {
    int tile = blockIdx.x, n = blockIdx.y;
    int l0 = tile * 64;
    __shared__ float attS[16*65];
    __shared__ float WoS[16*208];
    int tid = threadIdx.x, tx = tid & 31, tyq = tid >> 5;
    ull acc2[13][2];
    #pragma unroll
    for (int pa = 0; pa < 13; pa++) { acc2[pa][0] = 0ull; acc2[pa][1] = 0ull; }
    for (int k0 = 0; k0 < CIN*NSC; k0 += 16) {
        __syncthreads();
        for (int e = tid; e < 16*64; e += 256) {
            int li = e >> 4, kc = e & 15;
            int kk = k0 + kc;
            int u = kk / CIN, oc = kk - u*CIN;
            attS[kc*65 + li] = g_att[((size_t)(n*NSC + u)*LL + l0 + li)*CIN + oc];
        }
        for (int e = tid; e < 16*208; e += 256) {
            int kc = e / 208, co = e % 208;
            WoS[e] = (co < CIN) ? g_WoutT[(size_t)(k0 + kc)*CIN + co] : 0.f;
        }
        __syncthreads();
        #pragma unroll
        for (int kc = 0; kc < 16; kc++) {
            ull d0 = dup2f(attS[kc*65 + tx]);
            ull d1 = dup2f(attS[kc*65 + tx + 32]);
            #pragma unroll
            for (int pa = 0; pa < 13; pa++) {
                ull wp = ldp(&WoS[kc*208 + 2*tyq + 16*pa]);
                FMA2(acc2[pa][0], d0, wp);
                FMA2(acc2[pa][1], d1, wp);
            }
        }
    }
    #pragma unroll
    for (int pa = 0; pa < 13; pa++) {
        int co = 2*tyq + 16*pa;
        if (co + 1 < CIN) {
            float b0 = bout[co], b1 = bout[co + 1];
            #pragma unroll
            for (int b = 0; b < 2; b++) {
                int l = l0 + tx + 32*b;
                size_t i0 = ((size_t)n*CIN + co)*LL + l;
                float2 v = upk2(acc2[pa][b]);
                out[i0]      = v.x + b0 + input[i0];
                out[i0 + LL] = v.y + b1 + input[i0 + LL];
            }
        }
    }
}

// ---------------- launch ----------------
extern "C" void kernel_launch(void* const* d_in, const int* in_sizes, int n_in,
                              void* d_out, int out_size) {
    const float* input = (const float*)d_in[0];
    const int*   sem   = (const int*)d_in[1];
    const float* Wx    = (const float*)d_in[2];
    const float* Wy    = (const float*)d_in[3];
    const float* Wout  = (const float*)d_in[4];
    const float* bout  = (const float*)d_in[5];
    float* out = (float*)d_out;

    cudaFuncSetAttribute(attn_kernel, cudaFuncAttributeMaxDynamicSharedMemorySize, 102912);

    prep_kernel<<<640, 256>>>(Wx, Wy, Wout);
    conv_kernel<<<dim3(LL/64, NB), 256>>>(input);
    yembed_kernel<<<dim3(LL/64, NB), 256>>>(input);
    hist_kernel<<<dim3(NCHUNK, NSC, NB), 256>>>(sem);
    scatter_kernel<<<dim3(NSC, NB), 256>>>(sem);
    attn_kernel<<<dim3(KCL, NSC, NB), 256, 102912>>>();
    out_kernel<<<dim3(LL/64, NB), 256>>>(input, bout, out);
}

// round 6
// speedup vs baseline: 1.2982x; 1.0541x over previous
#include <cuda_runtime.h>
#include <cuda_bf16.h>
#include <math.h>

#define NB   2
#define CIN  200
#define CQ   50
#define LL   16384
#define NSC  4
#define WIN  64
#define KCL  256
#define NCHUNK 8
#define CHSZ 2048

typedef unsigned long long ull;

#define FMA2(acc, a, b) asm("fma.rn.f32x2 %0, %1, %2, %0;" : "+l"(acc) : "l"(a), "l"(b))

__device__ __forceinline__ ull dup2f(float x) {
    ull r; asm("mov.b64 %0, {%1, %1};" : "=l"(r) : "f"(x)); return r;
}
__device__ __forceinline__ float2 upk2(ull v) {
    float2 f; asm("mov.b64 {%0, %1}, %2;" : "=f"(f.x), "=f"(f.y) : "l"(v)); return f;
}
__device__ __forceinline__ ull ldp(const float* p) {
    return *reinterpret_cast<const ull*>(p);
}
__device__ __forceinline__ ull pk2(float x, float y) {
    ull r; asm("mov.b64 %0, {%1, %2};" : "=l"(r) : "f"(x), "f"(y)); return r;
}
// LDS.128: one quad -> two f32x2 operands
__device__ __forceinline__ void ldq(const float* p, ull& a, ull& b) {
    float4 v = *reinterpret_cast<const float4*>(p);
    a = pk2(v.x, v.y); b = pk2(v.z, v.w);
}

// ---------------- device scratch ----------------
__device__ float g_xembed[(size_t)NB*LL*CQ];        // [n][l][c]
__device__ float g_yembed[(size_t)NB*LL*CIN];       // [n][l][o]
__device__ float g_att[(size_t)NB*NSC*LL*CIN];      // [n][u][l][oc]
__device__ int   g_perm[NB*NSC*LL];
__device__ int   g_hist[NB*NSC*NCHUNK*32];
__device__ float g_WyT[CIN*CIN];                    // [c][o]
__device__ float g_WoutT[(CIN*NSC)*CIN];            // [k][co]
__device__ float g_WxT[CIN*9*64];                   // [c][tap][o(64, zero-pad)]

// ---------------- weight transposes ----------------
__global__ void prep_kernel(const float* __restrict__ Wx,
                            const float* __restrict__ Wy,
                            const float* __restrict__ Wout) {
    for (int i = blockIdx.x * blockDim.x + threadIdx.x; i < CIN*CIN*NSC;
         i += gridDim.x * blockDim.x) {
        if (i < CIN*CIN) {
            int o = i / CIN, c = i % CIN;
            g_WyT[c*CIN + o] = Wy[i];
        }
        {
            int co = i / (CIN*NSC), kk = i % (CIN*NSC);
            g_WoutT[(size_t)kk*CIN + co] = Wout[i];
        }
        if (i < CIN*9*64) {
            int c = i / 576, r = i % 576;
            int tap = r >> 6, o = r & 63;
            g_WxT[i] = (o < CQ) ? Wx[((size_t)o*CIN + c)*9 + tap] : 0.f;
        }
    }
}

// ---------------- conv3x3 reflect, 200->50, double-buffered, FFMA2 ----------------
__global__ __launch_bounds__(256) void conv_kernel(const float* __restrict__ input) {
    int tile = blockIdx.x, n = blockIdx.y;
    int l0 = tile * 64;
    int y = l0 >> 7, x0 = l0 & 127;
    __shared__ float inS[2][3*66];
    __shared__ float WxS[2][576];
    int tid = threadIdx.x, tx = tid & 15, ty = tid >> 4;
    ull acc2[4][2] = {{0ull,0ull},{0ull,0ull},{0ull,0ull},{0ull,0ull}};
    const float* inb = input + (size_t)n * CIN * LL;

    // precompute reflect address for this thread's halo element
    int in_off = -1;
    if (tid < 198) {
        int rr = tid / 66, cc = tid % 66;
        int gy = y - 1 + rr; gy = gy < 0 ? 1 : (gy > 127 ? 126 : gy);
        int gx = x0 - 1 + cc; gx = gx < 0 ? 1 : (gx > 127 ? 126 : gx);
        in_off = (gy << 7) + gx;
    }

    float wreg[3]; float ireg = 0.f;
    // prefetch c=0
    #pragma unroll
    for (int r = 0; r < 3; r++) { int e = tid + 256*r; if (e < 576) wreg[r] = g_WxT[e]; }
    if (in_off >= 0) ireg = inb[in_off];
    // commit to buf 0
    #pragma unroll
    for (int r = 0; r < 3; r++) { int e = tid + 256*r; if (e < 576) WxS[0][e] = wreg[r]; }
    if (in_off >= 0) inS[0][tid] = ireg;
    __syncthreads();

    for (int c = 0; c < CIN; ++c) {
        int p = c & 1;
        if (c + 1 < CIN) {   // prefetch next channel
            #pragma unroll
            for (int r = 0; r < 3; r++) { int e = tid + 256*r; if (e < 576) wreg[r] = g_WxT[(c+1)*576 + e]; }
            if (in_off >= 0) ireg = inb[(size_t)(c+1)*LL + in_off];
        }
        const float* W = WxS[p];
        const float* I = inS[p];
        #pragma unroll
        for (int ky = 0; ky < 3; ky++)
        #pragma unroll
        for (int kx = 0; kx < 3; kx++) {
            ull w0, w1; ldq(&W[(ky*3 + kx)*64 + 4*tx], w0, w1);
            #pragma unroll
            for (int a = 0; a < 4; a++) {
                ull iv = dup2f(I[ky*66 + ty + 16*a + kx]);
                FMA2(acc2[a][0], iv, w0);
                FMA2(acc2[a][1], iv, w1);
            }
        }
        if (c + 1 < CIN) {   // commit next (waits on prefetch regs only here)
            #pragma unroll
            for (int r = 0; r < 3; r++) { int e = tid + 256*r; if (e < 576) WxS[p^1][e] = wreg[r]; }
            if (in_off >= 0) inS[p^1][tid] = ireg;
        }
        __syncthreads();
    }
    #pragma unroll
    for (int a = 0; a < 4; a++) {
        int l = l0 + ty + 16*a;
        size_t base = ((size_t)n*LL + l)*CQ + 4*tx;
        if (4*tx + 1 < CQ)
            *reinterpret_cast<float2*>(&g_xembed[base]) = upk2(acc2[a][0]);
        if (4*tx + 3 < CQ)
            *reinterpret_cast<float2*>(&g_xembed[base + 2]) = upk2(acc2[a][1]);
    }
}

// ---------------- 1x1 Wy GEMM, wide loads, FFMA2 ----------------
// thread map: tx = l-lane (0..31), ty8 = col group (0..7)
__global__ __launch_bounds__(256) void yembed_kernel(const float* __restrict__ input) {
    int tile = blockIdx.x, n = blockIdx.y;
    int l0 = tile * 64;
    __shared__ float inS[64*18];      // [l][cc], stride 18
    __shared__ float WyS[16*208];
    int tid = threadIdx.x, tx = tid & 31, ty8 = tid >> 5;
    ull acc2[13][2];
    #pragma unroll
    for (int pa = 0; pa < 13; pa++) { acc2[pa][0] = 0ull; acc2[pa][1] = 0ull; }
    const float* inb = input + (size_t)n * CIN * LL;
    for (int cb = 0; cb < 208; cb += 16) {
        __syncthreads();
        for (int e = tid; e < 16*64; e += 256) {
            int cc = e >> 6, li = e & 63;
            inS[li*18 + cc] = (cb + cc < CIN) ? inb[(size_t)(cb + cc)*LL + l0 + li] : 0.f;
        }
        for (int e = tid; e < 16*208; e += 256) {
            int cc = e / 208, o = e % 208;
            WyS[e] = (o < CIN && cb + cc < CIN) ? g_WyT[(cb + cc)*CIN + o] : 0.f;
        }
        __syncthreads();
        #pragma unroll
        for (int c2 = 0; c2 < 8; c2++) {
            float2 i0 = upk2(ldp(&inS[tx*18 + 2*c2]));
            float2 i1 = upk2(ldp(&inS[(tx + 32)*18 + 2*c2]));
            #pragma unroll
            for (int h = 0; h < 2; h++) {
                int cc = 2*c2 + h;
                ull d0 = dup2f(h ? i0.y : i0.x);
                ull d1 = dup2f(h ? i1.y : i1.x);
                #pragma unroll
                for (int q = 0; q < 6; q++) {
                    ull w0, w1; ldq(&WyS[cc*208 + 4*ty8 + 32*q], w0, w1);
                    FMA2(acc2[2*q][0], d0, w0);   FMA2(acc2[2*q][1], d1, w0);
                    FMA2(acc2[2*q+1][0], d0, w1); FMA2(acc2[2*q+1][1], d1, w1);
                }
                ull wt = ldp(&WyS[cc*208 + 192 + 2*ty8]);
                FMA2(acc2[12][0], d0, wt); FMA2(acc2[12][1], d1, wt);
            }
        }
    }
    float* yb0 = &g_yembed[((size_t)n*LL + l0 + tx)*CIN];
    float* yb1 = &g_yembed[((size_t)n*LL + l0 + tx + 32)*CIN];
    #pragma unroll
    for (int q = 0; q < 6; q++) {
        int o = 4*ty8 + 32*q;
        float2 a0 = upk2(acc2[2*q][0]),   b0 = upk2(acc2[2*q+1][0]);
        float2 a1 = upk2(acc2[2*q][1]),   b1 = upk2(acc2[2*q+1][1]);
        *reinterpret_cast<float4*>(&yb0[o]) = make_float4(a0.x, a0.y, b0.x, b0.y);
        *reinterpret_cast<float4*>(&yb1[o]) = make_float4(a1.x, a1.y, b1.x, b1.y);
    }
    if (ty8 < 4) {
        int o = 192 + 2*ty8;
        *reinterpret_cast<float2*>(&yb0[o]) = upk2(acc2[12][0]);
        *reinterpret_cast<float2*>(&yb1[o]) = upk2(acc2[12][1]);
    }
}

// ---------------- sort: histogram ----------------
__global__ void hist_kernel(const int* __restrict__ sem) {
    int chunk = blockIdx.x, u = blockIdx.y, n = blockIdx.z;
    __shared__ int h[32];
    int tid = threadIdx.x;
    if (tid < 32) h[tid] = 0;
    __syncthreads();
    const int* lab = sem + (size_t)(n*NSC + u)*LL + chunk*CHSZ;
    for (int i = tid; i < CHSZ; i += 256) atomicAdd(&h[lab[i] & 31], 1);
    __syncthreads();
    if (tid < 32) g_hist[((n*NSC + u)*NCHUNK + chunk)*32 + tid] = h[tid];
}

// ---------------- sort: scan + stable scatter ----------------
__global__ void scatter_kernel(const int* __restrict__ sem) {
    int u = blockIdx.x, n = blockIdx.y;
    __shared__ int cnt[NCHUNK][32];
    __shared__ int start[NCHUNK][32];
    __shared__ int buf[NCHUNK][128];
    int tid = threadIdx.x;
    cnt[tid >> 5][tid & 31] = g_hist[((n*NSC + u)*NCHUNK + (tid >> 5))*32 + (tid & 31)];
    __syncthreads();
    if (tid < 32) {
        int tot = 0;
        #pragma unroll
        for (int ch = 0; ch < NCHUNK; ch++) tot += cnt[ch][tid];
        int inc = tot;
        #pragma unroll
        for (int off = 1; off < 32; off <<= 1) {
            int v = __shfl_up_sync(0xffffffffu, inc, off);
            if (tid >= off) inc += v;
        }
        int run = inc - tot;
        #pragma unroll
        for (int ch = 0; ch < NCHUNK; ch++) { start[ch][tid] = run; run += cnt[ch][tid]; }
    }
    __syncthreads();
    int w = tid >> 5, lane = tid & 31;
    int off = start[w][lane];
    const int* lab = sem + (size_t)(n*NSC + u)*LL + w*CHSZ;
    int* pout = g_perm + (n*NSC + u)*LL;
    for (int t0 = 0; t0 < CHSZ; t0 += 128) {
        #pragma unroll
        for (int j = 0; j < 4; j++) buf[w][lane*4 + j] = lab[t0 + lane*4 + j];
        __syncwarp();
        #pragma unroll 8
        for (int e = 0; e < 128; e++) {
            if (buf[w][e] == lane) { pout[off] = w*CHSZ + t0 + e; off++; }
        }
        __syncwarp();
    }
}

// ---------------- attention, wide loads, FFMA2 ----------------
// dyn smem: P[64][196] | region2 = max(KsT[50][196]+Qs[64][52], Vs[64][208])
__global__ __launch_bounds__(256) void attn_kernel() {
    extern __shared__ float sm[];
    float* P   = sm;                  // 64*196 = 12544
    float* Vs  = sm + 64*196;         // 64*208 = 13312
    float* KsT = Vs;                  // 50*196 = 9800
    float* Qs  = KsT + 50*196;        // 64*52  = 3328  (9800+3328 <= 13312)
    __shared__ int lperm[192];
    int k = blockIdx.x, u = blockIdx.y, n = blockIdx.z;
    int tid = threadIdx.x, tx = tid & 7, ty = tid >> 3;
    int r0 = ty, r1 = ty + 32;

    const int* pbase = g_perm + (n*NSC + u)*LL;
    if (tid < 192) {
        int jj = tid & 63;
        int kk = tid < 64 ? k : (tid < 128 ? (k + KCL - 1) & (KCL - 1) : (k + 1) & (KCL - 1));
        lperm[tid] = pbase[kk*WIN + jj];
    }
    __syncthreads();

    const float* xb = g_xembed + (size_t)n*LL*CQ;
    for (int e = tid; e < 192*CQ; e += 256) {
        int j = e / CQ, c = e - j*CQ;
        KsT[c*196 + j] = xb[(size_t)lperm[j]*CQ + c];
    }
    for (int e = tid; e < 64*25; e += 256) {
        int i = e / 25, c2 = e - i*25;
        *reinterpret_cast<float2*>(&Qs[i*52 + 2*c2]) =
            *reinterpret_cast<const float2*>(&xb[(size_t)lperm[i]*CQ + 2*c2]);
    }
    __syncthreads();
    if (tid < 192) {
        float ss = 0.f;
        #pragma unroll 10
        for (int c = 0; c < CQ; c++) { float v = KsT[c*196 + tid]; ss += v*v; }
        float s = 1.f / fmaxf(sqrtf(ss), 5e-5f);
        #pragma unroll 10
        for (int c = 0; c < CQ; c++) KsT[c*196 + tid] *= s;
    }
    __syncthreads();

    // S = Q @ K^T  (64 x 192, K=50); cols per thread: quads 4tx+32q
    {
        ull accS[2][12];
        #pragma unroll
        for (int pr = 0; pr < 12; pr++) { accS[0][pr] = 0ull; accS[1][pr] = 0ull; }
        #pragma unroll 5
        for (int c2 = 0; c2 < 25; c2++) {
            float2 q0 = upk2(ldp(&Qs[r0*52 + 2*c2]));
            float2 q1 = upk2(ldp(&Qs[r1*52 + 2*c2]));
            #pragma unroll
            for (int h = 0; h < 2; h++) {
                int c = 2*c2 + h;
                ull d0 = dup2f(h ? q0.y : q0.x);
                ull d1 = dup2f(h ? q1.y : q1.x);
                #pragma unroll
                for (int q = 0; q < 6; q++) {
                    ull k0, k1; ldq(&KsT[c*196 + 4*tx + 32*q], k0, k1);
                    FMA2(accS[0][2*q], d0, k0);   FMA2(accS[1][2*q], d1, k0);
                    FMA2(accS[0][2*q+1], d0, k1); FMA2(accS[1][2*q+1], d1, k1);
                }
            }
        }
        #pragma unroll
        for (int q = 0; q < 6; q++) {
            int col = 4*tx + 32*q;
            float2 a0 = upk2(accS[0][2*q]), b0 = upk2(accS[0][2*q+1]);
            float2 a1 = upk2(accS[1][2*q]), b1 = upk2(accS[1][2*q+1]);
            *reinterpret_cast<float4*>(&P[r0*196 + col]) = make_float4(a0.x, a0.y, b0.x, b0.y);
            *reinterpret_cast<float4*>(&P[r1*196 + col]) = make_float4(a1.x, a1.y, b1.x, b1.y);
        }
    }
    __syncthreads();

    // softmax over 192 cols
    {
        int r = tid >> 2, q = tid & 3;
        float* prow = P + r*196 + q*48;
        float mx = -1e30f;
        #pragma unroll 8
        for (int m = 0; m < 48; m++) mx = fmaxf(mx, prow[m]);
        mx = fmaxf(mx, __shfl_xor_sync(0xffffffffu, mx, 1));
        mx = fmaxf(mx, __shfl_xor_sync(0xffffffffu, mx, 2));
        float sum = 0.f;
        #pragma unroll 8
        for (int m = 0; m < 48; m++) { float e = __expf(prow[m] - mx); prow[m] = e; sum += e; }
        sum += __shfl_xor_sync(0xffffffffu, sum, 1);
        sum += __shfl_xor_sync(0xffffffffu, sum, 2);
        float inv = 1.f / sum;
        #pragma unroll 8
        for (int m = 0; m < 48; m++) prow[m] *= inv;
    }
    __syncthreads();
    // zero V pad cols (200..207)
    for (int e = tid; e < 64*8; e += 256) {
        int jj = e >> 3, cc = 200 + (e & 7);
        Vs[jj*208 + cc] = 0.f;
    }

    // O = P @ V, V staged in 64-row chunks
    ull accO[2][13];
    #pragma unroll
    for (int pr = 0; pr < 13; pr++) { accO[0][pr] = 0ull; accO[1][pr] = 0ull; }
    const float* yb = g_yembed + (size_t)n*LL*CIN;
    for (int ch = 0; ch < 3; ch++) {
        __syncthreads();
        for (int e = tid; e < 64*50; e += 256) {
            int jj = e / 50, c4 = e - jj*50;
            *reinterpret_cast<float4*>(&Vs[jj*208 + 4*c4]) =
                *reinterpret_cast<const float4*>(&yb[(size_t)lperm[ch*64 + jj]*CIN + 4*c4]);
        }
        __syncthreads();
        #pragma unroll 4
        for (int j2 = 0; j2 < 32; j2++) {
            float2 p0 = upk2(ldp(&P[r0*196 + ch*64 + 2*j2]));
            float2 p1 = upk2(ldp(&P[r1*196 + ch*64 + 2*j2]));
            #pragma unroll
            for (int h = 0; h < 2; h++) {
                int jj = 2*j2 + h;
                ull d0 = dup2f(h ? p0.y : p0.x);
                ull d1 = dup2f(h ? p1.y : p1.x);
                #pragma unroll
                for (int q = 0; q < 6; q++) {
                    ull v0, v1; ldq(&Vs[jj*208 + 4*tx + 32*q], v0, v1);
                    FMA2(accO[0][2*q], d0, v0);   FMA2(accO[1][2*q], d1, v0);
                    FMA2(accO[0][2*q+1], d0, v1); FMA2(accO[1][2*q+1], d1, v1);
                }
                ull vt = ldp(&Vs[jj*208 + 192 + 2*tx]);
                FMA2(accO[0][12], d0, vt); FMA2(accO[1][12], d1, vt);
            }
        }
    }
    float* ob = g_att + (size_t)(n*NSC + u)*LL*CIN;
    float* ob0 = ob + (size_t)lperm[r0]*CIN;
    float* ob1 = ob + (size_t)lperm[r1]*CIN;
    #pragma unroll
    for (int q = 0; q < 6; q++) {
        int c = 4*tx + 32*q;
        float2 a0 = upk2(accO[0][2*q]), b0 = upk2(accO[0][2*q+1]);
        float2 a1 = upk2(accO[1][2*q]), b1 = upk2(accO[1][2*q+1]);
        *reinterpret_cast<float4*>(&ob0[c]) = make_float4(a0.x, a0.y, b0.x, b0.y);
        *reinterpret_cast<float4*>(&ob1[c]) = make_float4(a1.x, a1.y, b1.x, b1.y);
    }
    if (tx < 4) {
        int c = 192 + 2*tx;
        *reinterpret_cast<float2*>(&ob0[c]) = upk2(accO[0][12]);
        *reinterpret_cast<float2*>(&ob1[c]) = upk2(accO[1][12]);
    }
}

// ---------------- Wout 1x1 (K=800) + bias + residual, wide loads ----------------
// thread map: tx = l-lane (0..31), tyq = col group (0..7)
__global__ __launch_bounds__(256) void out_kernel(const float* __restrict__ input,
                                                  const float* __restrict__ bout,
                                                  float* __restrict__ out) {
    int tile = blockIdx.x, n = blockIdx.y;
    int l0 = tile * 64;
    __shared__ float attS[64*34];     // [l][kc], stride 34
    __shared__ float WoS[32*208];
    int tid = threadIdx.x, tx = tid & 31, tyq = tid >> 5;
    ull acc2[13][2];
    #pragma unroll
    for (int pa = 0; pa < 13; pa++) { acc2[pa][0] = 0ull; acc2[pa][1] = 0ull; }
    for (int k0 = 0; k0 < CIN*NSC; k0 += 32) {
        __syncthreads();
        for (int e = tid; e < 32*64; e += 256) {
            int li = e >> 5, kc = e & 31;
            int kk = k0 + kc;
            int u = kk / CIN, oc = kk - u*CIN;
            attS[li*34 + kc] = g_att[((size_t)(n*NSC + u)*LL + l0 + li)*CIN + oc];
        }
        for (int e = tid; e < 32*208; e += 256) {
            int kc = e / 208, co = e % 208;
            WoS[e] = (co < CIN) ? g_WoutT[(size_t)(k0 + kc)*CIN + co] : 0.f;
        }
        __syncthreads();
        #pragma unroll
        for (int k2 = 0; k2 < 16; k2++) {
            float2 a0 = upk2(ldp(&attS[tx*34 + 2*k2]));
            float2 a1 = upk2(ldp(&attS[(tx + 32)*34 + 2*k2]));
            #pragma unroll
            for (int h = 0; h < 2; h++) {
                int kc = 2*k2 + h;
                ull d0 = dup2f(h ? a0.y : a0.x);
                ull d1 = dup2f(h ? a1.y : a1.x);
                #pragma unroll
                for (int q = 0; q < 6; q++) {
                    ull w0, w1; ldq(&WoS[kc*208 + 4*tyq + 32*q], w0, w1);
                    FMA2(acc2[2*q][0], d0, w0);   FMA2(acc2[2*q][1], d1, w0);
                    FMA2(acc2[2*q+1][0], d0, w1); FMA2(acc2[2*q+1][1], d1, w1);
                }
                ull wt = ldp(&WoS[kc*208 + 192 + 2*tyq]);
                FMA2(acc2[12][0], d0, wt); FMA2(acc2[12][1], d1, wt);
            }
        }
    }
    #pragma unroll
    for (int pa = 0; pa < 13; pa++) {
        int co;
        if (pa < 12) co = 4*tyq + 32*(pa >> 1) + 2*(pa & 1);
        else { if (tyq >= 4) break; co = 192 + 2*tyq; }
        float b0 = bout[co], b1 = bout[co + 1];
        #pragma unroll
        for (int b = 0; b < 2; b++) {
            int l = l0 + tx + 32*b;
            size_t i0 = ((size_t)n*CIN + co)*LL + l;
            float2 v = upk2(acc2[pa][b]);
            out[i0]      = v.x + b0 + input[i0];
            out[i0 + LL] = v.y + b1 + input[i0 + LL];
        }
    }
}

// ---------------- launch ----------------
extern "C" void kernel_launch(void* const* d_in, const int* in_sizes, int n_in,
                              void* d_out, int out_size) {
    const float* input = (const float*)d_in[0];
    const int*   sem   = (const int*)d_in[1];
    const float* Wx    = (const float*)d_in[2];
    const float* Wy    = (const float*)d_in[3];
    const float* Wout  = (const float*)d_in[4];
    const float* bout  = (const float*)d_in[5];
    float* out = (float*)d_out;

    cudaFuncSetAttribute(attn_kernel, cudaFuncAttributeMaxDynamicSharedMemorySize, 103424);

    prep_kernel<<<640, 256>>>(Wx, Wy, Wout);
    conv_kernel<<<dim3(LL/64, NB), 256>>>(input);
    yembed_kernel<<<dim3(LL/64, NB), 256>>>(input);
    hist_kernel<<<dim3(NCHUNK, NSC, NB), 256>>>(sem);
    scatter_kernel<<<dim3(NSC, NB), 256>>>(sem);
    attn_kernel<<<dim3(KCL, NSC, NB), 256, 103424>>>();
    out_kernel<<<dim3(LL/64, NB), 256>>>(input, bout, out);
}

// round 7
// speedup vs baseline: 1.4328x; 1.1037x over previous
#include <cuda_runtime.h>
#include <cuda_bf16.h>
#include <math.h>

#define NB   2
#define CIN  200
#define CQ   50
#define LL   16384
#define NSC  4
#define WIN  64
#define KCL  256
#define NCHUNK 8
#define CHSZ 2048

typedef unsigned long long ull;

#define FMA2(acc, a, b) asm("fma.rn.f32x2 %0, %1, %2, %0;" : "+l"(acc) : "l"(a), "l"(b))
#define CP_COMMIT() asm volatile("cp.async.commit_group;")
#define CP_WAIT1()  asm volatile("cp.async.wait_group 1;")
#define CP_WAIT0()  asm volatile("cp.async.wait_group 0;")

__device__ __forceinline__ ull dup2f(float x) {
    ull r; asm("mov.b64 %0, {%1, %1};" : "=l"(r) : "f"(x)); return r;
}
__device__ __forceinline__ float2 upk2(ull v) {
    float2 f; asm("mov.b64 {%0, %1}, %2;" : "=f"(f.x), "=f"(f.y) : "l"(v)); return f;
}
__device__ __forceinline__ ull ldp(const float* p) {
    return *reinterpret_cast<const ull*>(p);
}
__device__ __forceinline__ ull pk2(float x, float y) {
    ull r; asm("mov.b64 %0, {%1, %2};" : "=l"(r) : "f"(x), "f"(y)); return r;
}
__device__ __forceinline__ void ldq(const float* p, ull& a, ull& b) {
    float4 v = *reinterpret_cast<const float4*>(p);
    a = pk2(v.x, v.y); b = pk2(v.z, v.w);
}
__device__ __forceinline__ unsigned s2u(const void* p) {
    unsigned a;
    asm("{ .reg .u64 t; cvta.to.shared.u64 t, %1; cvt.u32.u64 %0, t; }" : "=r"(a) : "l"(p));
    return a;
}
__device__ __forceinline__ void cpa16(unsigned dst, const void* src) {
    asm volatile("cp.async.cg.shared.global [%0], [%1], 16;" :: "r"(dst), "l"(src));
}

// ---------------- device scratch ----------------
__device__ float g_xembed[(size_t)NB*LL*CQ];        // [n][l][c]
__device__ float g_yembed[(size_t)NB*LL*CIN];       // [n][l][o]
__device__ float g_att[(size_t)NB*NSC*LL*CIN];      // [n][u][l][oc]
__device__ int   g_perm[NB*NSC*LL];
__device__ float g_WyT[CIN*CIN];                    // [c][o]
__device__ float g_WoutT[(CIN*NSC)*CIN];            // [k][co]
__device__ float g_WxT[CIN*9*64];                   // [c][tap][o(64, zero-pad)]

// ---------------- prep (weight transposes) + counting sort, fused ----------------
__global__ void sortprep_kernel(const int* __restrict__ sem,
                                const float* __restrict__ Wx,
                                const float* __restrict__ Wy,
                                const float* __restrict__ Wout) {
    int u = blockIdx.x, n = blockIdx.y;
    int b = n*NSC + u;
    int tid = threadIdx.x;

    // weight transposes, strided over all 8 blocks
    for (int i = b*256 + tid; i < CIN*CIN*NSC; i += NSC*NB*256) {
        if (i < CIN*CIN) {
            int o = i / CIN, c = i % CIN;
            g_WyT[c*CIN + o] = Wy[i];
        }
        {
            int co = i / (CIN*NSC), kk = i % (CIN*NSC);
            g_WoutT[(size_t)kk*CIN + co] = Wout[i];
        }
        if (i < CIN*9*64) {
            int c = i / 576, r = i % 576;
            int tap = r >> 6, o = r & 63;
            g_WxT[i] = (o < CQ) ? Wx[((size_t)o*CIN + c)*9 + tap] : 0.f;
        }
    }

    // stable 32-bin counting sort for this (n,u)
    __shared__ int cnt[NCHUNK][32];
    __shared__ int start[NCHUNK][32];
    __shared__ int buf[NCHUNK][128];
    int w = tid >> 5, lane = tid & 31;
    cnt[w][lane] = 0;
    __syncthreads();
    const int* lab = sem + (size_t)b*LL + w*CHSZ;
    for (int i = lane; i < CHSZ; i += 32) atomicAdd(&cnt[w][lab[i] & 31], 1);
    __syncthreads();
    if (tid < 32) {
        int tot = 0;
        #pragma unroll
        for (int ch = 0; ch < NCHUNK; ch++) tot += cnt[ch][tid];
        int inc = tot;
        #pragma unroll
        for (int off = 1; off < 32; off <<= 1) {
            int v = __shfl_up_sync(0xffffffffu, inc, off);
            if (tid >= off) inc += v;
        }
        int run = inc - tot;
        #pragma unroll
        for (int ch = 0; ch < NCHUNK; ch++) { start[ch][tid] = run; run += cnt[ch][tid]; }
    }
    __syncthreads();
    int off = start[w][lane];
    int* pout = g_perm + b*LL;
    for (int t0 = 0; t0 < CHSZ; t0 += 128) {
        #pragma unroll
        for (int j = 0; j < 4; j++) buf[w][lane*4 + j] = lab[t0 + lane*4 + j];
        __syncwarp();
        #pragma unroll 8
        for (int e = 0; e < 128; e++) {
            if (buf[w][e] == lane) { pout[off] = w*CHSZ + t0 + e; off++; }
        }
        __syncwarp();
    }
}

// ---------------- conv3x3 reflect, 200->50, double-buffered, FFMA2 ----------------
__global__ __launch_bounds__(256) void conv_kernel(const float* __restrict__ input) {
    int tile = blockIdx.x, n = blockIdx.y;
    int l0 = tile * 64;
    int y = l0 >> 7, x0 = l0 & 127;
    __shared__ float inS[2][3*66];
    __shared__ float WxS[2][576];
    int tid = threadIdx.x, tx = tid & 15, ty = tid >> 4;
    ull acc2[4][2] = {{0ull,0ull},{0ull,0ull},{0ull,0ull},{0ull,0ull}};
    const float* inb = input + (size_t)n * CIN * LL;

    int in_off = -1;
    if (tid < 198) {
        int rr = tid / 66, cc = tid % 66;
        int gy = y - 1 + rr; gy = gy < 0 ? 1 : (gy > 127 ? 126 : gy);
        int gx = x0 - 1 + cc; gx = gx < 0 ? 1 : (gx > 127 ? 126 : gx);
        in_off = (gy << 7) + gx;
    }

    float wreg[3]; float ireg = 0.f;
    #pragma unroll
    for (int r = 0; r < 3; r++) { int e = tid + 256*r; if (e < 576) wreg[r] = g_WxT[e]; }
    if (in_off >= 0) ireg = inb[in_off];
    #pragma unroll
    for (int r = 0; r < 3; r++) { int e = tid + 256*r; if (e < 576) WxS[0][e] = wreg[r]; }
    if (in_off >= 0) inS[0][tid] = ireg;
    __syncthreads();

    for (int c = 0; c < CIN; ++c) {
        int p = c & 1;
        if (c + 1 < CIN) {
            #pragma unroll
            for (int r = 0; r < 3; r++) { int e = tid + 256*r; if (e < 576) wreg[r] = g_WxT[(c+1)*576 + e]; }
            if (in_off >= 0) ireg = inb[(size_t)(c+1)*LL + in_off];
        }
        const float* W = WxS[p];
        const float* I = inS[p];
        #pragma unroll
        for (int ky = 0; ky < 3; ky++)
        #pragma unroll
        for (int kx = 0; kx < 3; kx++) {
            ull w0, w1; ldq(&W[(ky*3 + kx)*64 + 4*tx], w0, w1);
            #pragma unroll
            for (int a = 0; a < 4; a++) {
                ull iv = dup2f(I[ky*66 + ty + 16*a + kx]);
                FMA2(acc2[a][0], iv, w0);
                FMA2(acc2[a][1], iv, w1);
            }
        }
        if (c + 1 < CIN) {
            #pragma unroll
            for (int r = 0; r < 3; r++) { int e = tid + 256*r; if (e < 576) WxS[p^1][e] = wreg[r]; }
            if (in_off >= 0) inS[p^1][tid] = ireg;
        }
        __syncthreads();
    }
    #pragma unroll
    for (int a = 0; a < 4; a++) {
        int l = l0 + ty + 16*a;
        size_t base = ((size_t)n*LL + l)*CQ + 4*tx;
        if (4*tx + 1 < CQ)
            *reinterpret_cast<float2*>(&g_xembed[base]) = upk2(acc2[a][0]);
        if (4*tx + 3 < CQ)
            *reinterpret_cast<float2*>(&g_xembed[base + 2]) = upk2(acc2[a][1]);
    }
}

// ---------------- 1x1 Wy GEMM, wide loads, FFMA2 ----------------
__global__ __launch_bounds__(256) void yembed_kernel(const float* __restrict__ input) {
    int tile = blockIdx.x, n = blockIdx.y;
    int l0 = tile * 64;
    __shared__ float inS[64*18];
    __shared__ float WyS[16*208];
    int tid = threadIdx.x, tx = tid & 31, ty8 = tid >> 5;
    ull acc2[13][2];
    #pragma unroll
    for (int pa = 0; pa < 13; pa++) { acc2[pa][0] = 0ull; acc2[pa][1] = 0ull; }
    const float* inb = input + (size_t)n * CIN * LL;
    for (int cb = 0; cb < 208; cb += 16) {
        __syncthreads();
        for (int e = tid; e < 16*64; e += 256) {
            int cc = e >> 6, li = e & 63;
            inS[li*18 + cc] = (cb + cc < CIN) ? inb[(size_t)(cb + cc)*LL + l0 + li] : 0.f;
        }
        for (int e = tid; e < 16*208; e += 256) {
            int cc = e / 208, o = e % 208;
            WyS[e] = (o < CIN && cb + cc < CIN) ? g_WyT[(cb + cc)*CIN + o] : 0.f;
        }
        __syncthreads();
        #pragma unroll
        for (int c2 = 0; c2 < 8; c2++) {
            float2 i0 = upk2(ldp(&inS[tx*18 + 2*c2]));
            float2 i1 = upk2(ldp(&inS[(tx + 32)*18 + 2*c2]));
            #pragma unroll
            for (int h = 0; h < 2; h++) {
                int cc = 2*c2 + h;
                ull d0 = dup2f(h ? i0.y : i0.x);
                ull d1 = dup2f(h ? i1.y : i1.x);
                #pragma unroll
                for (int q = 0; q < 6; q++) {
                    ull w0, w1; ldq(&WyS[cc*208 + 4*ty8 + 32*q], w0, w1);
                    FMA2(acc2[2*q][0], d0, w0);   FMA2(acc2[2*q][1], d1, w0);
                    FMA2(acc2[2*q+1][0], d0, w1); FMA2(acc2[2*q+1][1], d1, w1);
                }
                ull wt = ldp(&WyS[cc*208 + 192 + 2*ty8]);
                FMA2(acc2[12][0], d0, wt); FMA2(acc2[12][1], d1, wt);
            }
        }
    }
    float* yb0 = &g_yembed[((size_t)n*LL + l0 + tx)*CIN];
    float* yb1 = &g_yembed[((size_t)n*LL + l0 + tx + 32)*CIN];
    #pragma unroll
    for (int q = 0; q < 6; q++) {
        int o = 4*ty8 + 32*q;
        float2 a0 = upk2(acc2[2*q][0]),   b0 = upk2(acc2[2*q+1][0]);
        float2 a1 = upk2(acc2[2*q][1]),   b1 = upk2(acc2[2*q+1][1]);
        *reinterpret_cast<float4*>(&yb0[o]) = make_float4(a0.x, a0.y, b0.x, b0.y);
        *reinterpret_cast<float4*>(&yb1[o]) = make_float4(a1.x, a1.y, b1.x, b1.y);
    }
    if (ty8 < 4) {
        int o = 192 + 2*ty8;
        *reinterpret_cast<float2*>(&yb0[o]) = upk2(acc2[12][0]);
        *reinterpret_cast<float2*>(&yb1[o]) = upk2(acc2[12][1]);
    }
}

// ---------------- attention, cp.async double-buffered V ----------------
// dyn smem: P[64][196] | V: 2 x [32][208]; KsT[50][196]+Qs[64][52] alias the V region
__global__ __launch_bounds__(256) void attn_kernel() {
    extern __shared__ float sm[];
    float* P   = sm;                  // 12544 fl
    float* Vs  = sm + 64*196;         // 2 x 6656 fl
    float* KsT = Vs;                  // 9800 fl
    float* Qs  = KsT + 50*196;        // 3328 fl
    __shared__ int lperm[192];
    int k = blockIdx.x, u = blockIdx.y, n = blockIdx.z;
    int tid = threadIdx.x, tx = tid & 7, ty = tid >> 3;
    int r0 = ty, r1 = ty + 32;

    const int* pbase = g_perm + (n*NSC + u)*LL;
    if (tid < 192) {
        int jj = tid & 63;
        int kk = tid < 64 ? k : (tid < 128 ? (k + KCL - 1) & (KCL - 1) : (k + 1) & (KCL - 1));
        lperm[tid] = pbase[kk*WIN + jj];
    }
    __syncthreads();

    const float* xb = g_xembed + (size_t)n*LL*CQ;
    for (int e = tid; e < 192*CQ; e += 256) {
        int j = e / CQ, c = e - j*CQ;
        KsT[c*196 + j] = xb[(size_t)lperm[j]*CQ + c];
    }
    for (int e = tid; e < 64*25; e += 256) {
        int i = e / 25, c2 = e - i*25;
        *reinterpret_cast<float2*>(&Qs[i*52 + 2*c2]) =
            *reinterpret_cast<const float2*>(&xb[(size_t)lperm[i]*CQ + 2*c2]);
    }
    __syncthreads();
    if (tid < 192) {
        float ss = 0.f;
        #pragma unroll 10
        for (int c = 0; c < CQ; c++) { float v = KsT[c*196 + tid]; ss += v*v; }
        float s = 1.f / fmaxf(sqrtf(ss), 5e-5f);
        #pragma unroll 10
        for (int c = 0; c < CQ; c++) KsT[c*196 + tid] *= s;
    }
    __syncthreads();

    // S = Q @ K^T
    {
        ull accS[2][12];
        #pragma unroll
        for (int pr = 0; pr < 12; pr++) { accS[0][pr] = 0ull; accS[1][pr] = 0ull; }
        #pragma unroll 5
        for (int c2 = 0; c2 < 25; c2++) {
            float2 q0 = upk2(ldp(&Qs[r0*52 + 2*c2]));
            float2 q1 = upk2(ldp(&Qs[r1*52 + 2*c2]));
            #pragma unroll
            for (int h = 0; h < 2; h++) {
                int c = 2*c2 + h;
                ull d0 = dup2f(h ? q0.y : q0.x);
                ull d1 = dup2f(h ? q1.y : q1.x);
                #pragma unroll
                for (int q = 0; q < 6; q++) {
                    ull k0, k1; ldq(&KsT[c*196 + 4*tx + 32*q], k0, k1);
                    FMA2(accS[0][2*q], d0, k0);   FMA2(accS[1][2*q], d1, k0);
                    FMA2(accS[0][2*q+1], d0, k1); FMA2(accS[1][2*q+1], d1, k1);
                }
            }
        }
        #pragma unroll
        for (int q = 0; q < 6; q++) {
            int col = 4*tx + 32*q;
            float2 a0 = upk2(accS[0][2*q]), b0 = upk2(accS[0][2*q+1]);
            float2 a1 = upk2(accS[1][2*q]), b1 = upk2(accS[1][2*q+1]);
            *reinterpret_cast<float4*>(&P[r0*196 + col]) = make_float4(a0.x, a0.y, b0.x, b0.y);
            *reinterpret_cast<float4*>(&P[r1*196 + col]) = make_float4(a1.x, a1.y, b1.x, b1.y);
        }
    }
    __syncthreads();   // KsT/Qs dead after this point

    const float* yb = g_yembed + (size_t)n*LL*CIN;
    // issue async V loads for chunks 0,1 (overlap with softmax)
    #pragma unroll
    for (int c0 = 0; c0 < 2; c0++) {
        unsigned vb = s2u(Vs + c0*6656);
        for (int e = tid; e < 32*50; e += 256) {
            int row = e / 50, qd = e - row*50;
            cpa16(vb + (row*208 + 4*qd)*4,
                  yb + (size_t)lperm[c0*32 + row]*CIN + 4*qd);
        }
        CP_COMMIT();
    }
    // zero V pad cols (200..207) in both buffers (disjoint from cp.async targets)
    for (int e = tid; e < 512; e += 256) {
        int bfr = e >> 8, r = (e >> 3) & 31, c = e & 7;
        Vs[bfr*6656 + r*208 + 200 + c] = 0.f;
    }
    // softmax over 192 cols (overlaps with in-flight V loads)
    {
        int r = tid >> 2, q = tid & 3;
        float* prow = P + r*196 + q*48;
        float mx = -1e30f;
        #pragma unroll 8
        for (int m = 0; m < 48; m++) mx = fmaxf(mx, prow[m]);
        mx = fmaxf(mx, __shfl_xor_sync(0xffffffffu, mx, 1));
        mx = fmaxf(mx, __shfl_xor_sync(0xffffffffu, mx, 2));
        float sum = 0.f;
        #pragma unroll 8
        for (int m = 0; m < 48; m++) { float e = __expf(prow[m] - mx); prow[m] = e; sum += e; }
        sum += __shfl_xor_sync(0xffffffffu, sum, 1);
        sum += __shfl_xor_sync(0xffffffffu, sum, 2);
        float inv = 1.f / sum;
        #pragma unroll 8
        for (int m = 0; m < 48; m++) prow[m] *= inv;
    }

    // O = P @ V, 6 chunks of 32 rows, ping-pong buffers
    ull accO[2][13];
    #pragma unroll
    for (int pr = 0; pr < 13; pr++) { accO[0][pr] = 0ull; accO[1][pr] = 0ull; }
    for (int ch = 0; ch < 6; ch++) {
        if (ch < 5) CP_WAIT1(); else CP_WAIT0();
        __syncthreads();
        const float* V = Vs + (ch & 1)*6656;
        #pragma unroll 4
        for (int j2 = 0; j2 < 16; j2++) {
            float2 p0 = upk2(ldp(&P[r0*196 + ch*32 + 2*j2]));
            float2 p1 = upk2(ldp(&P[r1*196 + ch*32 + 2*j2]));
            #pragma unroll
            for (int h = 0; h < 2; h++) {
                int jj = 2*j2 + h;
                ull d0 = dup2f(h ? p0.y : p0.x);
                ull d1 = dup2f(h ? p1.y : p1.x);
                #pragma unroll
                for (int q = 0; q < 6; q++) {
                    ull v0, v1; ldq(&V[jj*208 + 4*tx + 32*q], v0, v1);
                    FMA2(accO[0][2*q], d0, v0);   FMA2(accO[1][2*q], d1, v0);
                    FMA2(accO[0][2*q+1], d0, v1); FMA2(accO[1][2*q+1], d1, v1);
                }
                ull vt = ldp(&V[jj*208 + 192 + 2*tx]);
                FMA2(accO[0][12], d0, vt); FMA2(accO[1][12], d1, vt);
            }
        }
        __syncthreads();
        if (ch + 2 < 6) {
            unsigned vb = s2u(Vs + (ch & 1)*6656);
            for (int e = tid; e < 32*50; e += 256) {
                int row = e / 50, qd = e - row*50;
                cpa16(vb + (row*208 + 4*qd)*4,
                      yb + (size_t)lperm[(ch + 2)*32 + row]*CIN + 4*qd);
            }
            CP_COMMIT();
        }
    }
    float* ob = g_att + (size_t)(n*NSC + u)*LL*CIN;
    float* ob0 = ob + (size_t)lperm[r0]*CIN;
    float* ob1 = ob + (size_t)lperm[r1]*CIN;
    #pragma unroll
    for (int q = 0; q < 6; q++) {
        int c = 4*tx + 32*q;
        float2 a0 = upk2(accO[0][2*q]), b0 = upk2(accO[0][2*q+1]);
        float2 a1 = upk2(accO[1][2*q]), b1 = upk2(accO[1][2*q+1]);
        *reinterpret_cast<float4*>(&ob0[c]) = make_float4(a0.x, a0.y, b0.x, b0.y);
        *reinterpret_cast<float4*>(&ob1[c]) = make_float4(a1.x, a1.y, b1.x, b1.y);
    }
    if (tx < 4) {
        int c = 192 + 2*tx;
        *reinterpret_cast<float2*>(&ob0[c]) = upk2(accO[0][12]);
        *reinterpret_cast<float2*>(&ob1[c]) = upk2(accO[1][12]);
    }
}

// ---------------- Wout 1x1 (K=800) + bias + residual, cp.async double-buffered ----------------
// dyn smem: attB 2 x [64][36] | WoB 2 x [32][208]
__global__ __launch_bounds__(256) void out_kernel(const float* __restrict__ input,
                                                  const float* __restrict__ bout,
                                                  float* __restrict__ out) {
    extern __shared__ float osm[];
    float* attB = osm;                 // 2 x 2304 fl
    float* WoB  = osm + 2*2304;        // 2 x 6656 fl
    int tile = blockIdx.x, n = blockIdx.y;
    int l0 = tile * 64;
    int tid = threadIdx.x, tx = tid & 31, tyq = tid >> 5;
    ull acc2[13][2];
    #pragma unroll
    for (int pa = 0; pa < 13; pa++) { acc2[pa][0] = 0ull; acc2[pa][1] = 0ull; }

    // async stage loader for K-chunk (k0 = 32*c), buffer bfr
    auto issue = [&](int c, int bfr) {
        int k0 = c*32;
        unsigned ab = s2u(attB + bfr*2304);
        for (int e = tid; e < 512; e += 256) {
            int li = e >> 3, qd = e & 7;
            int kc = 4*qd, kk = k0 + kc;
            int u = kk / CIN, oc = kk - u*CIN;
            cpa16(ab + (li*36 + kc)*4,
                  g_att + ((size_t)(n*NSC + u)*LL + l0 + li)*CIN + oc);
        }
        unsigned wb = s2u(WoB + bfr*6656);
        for (int e = tid; e < 1600; e += 256) {
            int kc = e / 50, qd = e - kc*50;
            cpa16(wb + (kc*208 + 4*qd)*4,
                  g_WoutT + (size_t)(k0 + kc)*CIN + 4*qd);
        }
        CP_COMMIT();
    };

    issue(0, 0);
    issue(1, 1);
    for (int c = 0; c < 25; c++) {
        if (c < 24) CP_WAIT1(); else CP_WAIT0();
        __syncthreads();
        const float* aS = attB + (c & 1)*2304;
        const float* wS = WoB + (c & 1)*6656;
        #pragma unroll
        for (int k2 = 0; k2 < 16; k2++) {
            float2 a0 = upk2(ldp(&aS[tx*36 + 2*k2]));
            float2 a1 = upk2(ldp(&aS[(tx + 32)*36 + 2*k2]));
            #pragma unroll
            for (int h = 0; h < 2; h++) {
                ull d0 = dup2f(h ? a0.y : a0.x);
                ull d1 = dup2f(h ? a1.y : a1.x);
                int kc = 2*k2 + h;
                #pragma unroll
                for (int q = 0; q < 6; q++) {
                    ull w0, w1; ldq(&wS[kc*208 + 4*tyq + 32*q], w0, w1);
                    FMA2(acc2[2*q][0], d0, w0);   FMA2(acc2[2*q][1], d1, w0);
                    FMA2(acc2[2*q+1][0], d0, w1); FMA2(acc2[2*q+1][1], d1, w1);
                }
                if (tyq < 4) {                    // cols 192..199 only (others unloaded)
                    ull wt = ldp(&wS[kc*208 + 192 + 2*tyq]);
                    FMA2(acc2[12][0], d0, wt); FMA2(acc2[12][1], d1, wt);
                }
            }
        }
        __syncthreads();
        if (c + 2 < 25) issue(c + 2, c & 1);
    }
    #pragma unroll
    for (int pa = 0; pa < 13; pa++) {
        int co;
        if (pa < 12) co = 4*tyq + 32*(pa >> 1) + 2*(pa & 1);
        else { if (tyq >= 4) break; co = 192 + 2*tyq; }
        float b0 = bout[co], b1 = bout[co + 1];
        #pragma unroll
        for (int b = 0; b < 2; b++) {
            int l = l0 + tx + 32*b;
            size_t i0 = ((size_t)n*CIN + co)*LL + l;
            float2 v = upk2(acc2[pa][b]);
            out[i0]      = v.x + b0 + input[i0];
            out[i0 + LL] = v.y + b1 + input[i0 + LL];
        }
    }
}

// ---------------- launch ----------------
extern "C" void kernel_launch(void* const* d_in, const int* in_sizes, int n_in,
                              void* d_out, int out_size) {
    const float* input = (const float*)d_in[0];
    const int*   sem   = (const int*)d_in[1];
    const float* Wx    = (const float*)d_in[2];
    const float* Wy    = (const float*)d_in[3];
    const float* Wout  = (const float*)d_in[4];
    const float* bout  = (const float*)d_in[5];
    float* out = (float*)d_out;

    cudaFuncSetAttribute(attn_kernel, cudaFuncAttributeMaxDynamicSharedMemorySize, 103424);
    cudaFuncSetAttribute(out_kernel,  cudaFuncAttributeMaxDynamicSharedMemorySize, 71680);

    sortprep_kernel<<<dim3(NSC, NB), 256>>>(sem, Wx, Wy, Wout);
    conv_kernel<<<dim3(LL/64, NB), 256>>>(input);
    yembed_kernel<<<dim3(LL/64, NB), 256>>>(input);
    attn_kernel<<<dim3(KCL, NSC, NB), 256, 103424>>>();
    out_kernel<<<dim3(LL/64, NB), 256, 71680>>>(input, bout, out);
}

// round 8
// speedup vs baseline: 1.5360x; 1.0720x over previous
#include <cuda_runtime.h>
#include <cuda_bf16.h>
#include <math.h>

#define NB   2
#define CIN  200
#define CQ   50
#define LL   16384
#define NSC  4
#define WIN  64
#define KCL  256
#define NCHUNK 8
#define CHSZ 2048

typedef unsigned long long ull;

#define FMA2(acc, a, b) asm("fma.rn.f32x2 %0, %1, %2, %0;" : "+l"(acc) : "l"(a), "l"(b))
#define CP_COMMIT() asm volatile("cp.async.commit_group;")
#define CP_WAIT1()  asm volatile("cp.async.wait_group 1;")
#define CP_WAIT0()  asm volatile("cp.async.wait_group 0;")

__device__ __forceinline__ ull dup2f(float x) {
    ull r; asm("mov.b64 %0, {%1, %1};" : "=l"(r) : "f"(x)); return r;
}
__device__ __forceinline__ float2 upk2(ull v) {
    float2 f; asm("mov.b64 {%0, %1}, %2;" : "=f"(f.x), "=f"(f.y) : "l"(v)); return f;
}
__device__ __forceinline__ ull ldp(const float* p) {
    return *reinterpret_cast<const ull*>(p);
}
__device__ __forceinline__ ull pk2(float x, float y) {
    ull r; asm("mov.b64 %0, {%1, %2};" : "=l"(r) : "f"(x), "f"(y)); return r;
}
__device__ __forceinline__ void ldq(const float* p, ull& a, ull& b) {
    float4 v = *reinterpret_cast<const float4*>(p);
    a = pk2(v.x, v.y); b = pk2(v.z, v.w);
}
__device__ __forceinline__ float4 q2(ull a, ull b) {
    float2 x = upk2(a), y = upk2(b);
    return make_float4(x.x, x.y, y.x, y.y);
}
__device__ __forceinline__ unsigned s2u(const void* p) {
    unsigned a;
    asm("{ .reg .u64 t; cvta.to.shared.u64 t, %1; cvt.u32.u64 %0, t; }" : "=r"(a) : "l"(p));
    return a;
}
__device__ __forceinline__ void cpa16(unsigned dst, const void* src) {
    asm volatile("cp.async.cg.shared.global [%0], [%1], 16;" :: "r"(dst), "l"(src));
}

// ---------------- device scratch ----------------
__device__ float g_xembed[(size_t)NB*LL*CQ];        // [n][l][c]
__device__ float g_yembed[(size_t)NB*LL*CIN];       // [n][l][o]
__device__ float g_att[(size_t)NB*NSC*LL*CIN];      // [n][u][l][oc]
__device__ int   g_perm[NB*NSC*LL];
__device__ float g_WyT[CIN*CIN];                    // [c][o]
__device__ float g_WoutT[(CIN*NSC)*CIN];            // [k][co]
__device__ float g_WxT[CIN*9*64];                   // [c][tap][o(64, zero-pad)]

// ---------------- prep (weight transposes) + counting sort, fused ----------------
__global__ void sortprep_kernel(const int* __restrict__ sem,
                                const float* __restrict__ Wx,
                                const float* __restrict__ Wy,
                                const float* __restrict__ Wout) {
    int u = blockIdx.x, n = blockIdx.y;
    int b = n*NSC + u;
    int tid = threadIdx.x;

    for (int i = b*256 + tid; i < CIN*CIN*NSC; i += NSC*NB*256) {
        if (i < CIN*CIN) {
            int o = i / CIN, c = i % CIN;
            g_WyT[c*CIN + o] = Wy[i];
        }
        {
            int co = i / (CIN*NSC), kk = i % (CIN*NSC);
            g_WoutT[(size_t)kk*CIN + co] = Wout[i];
        }
        if (i < CIN*9*64) {
            int c = i / 576, r = i % 576;
            int tap = r >> 6, o = r & 63;
            g_WxT[i] = (o < CQ) ? Wx[((size_t)o*CIN + c)*9 + tap] : 0.f;
        }
    }

    __shared__ int cnt[NCHUNK][32];
    __shared__ int start[NCHUNK][32];
    __shared__ int buf[NCHUNK][128];
    int w = tid >> 5, lane = tid & 31;
    cnt[w][lane] = 0;
    __syncthreads();
    const int* lab = sem + (size_t)b*LL + w*CHSZ;
    for (int i = lane; i < CHSZ; i += 32) atomicAdd(&cnt[w][lab[i] & 31], 1);
    __syncthreads();
    if (tid < 32) {
        int tot = 0;
        #pragma unroll
        for (int ch = 0; ch < NCHUNK; ch++) tot += cnt[ch][tid];
        int inc = tot;
        #pragma unroll
        for (int off = 1; off < 32; off <<= 1) {
            int v = __shfl_up_sync(0xffffffffu, inc, off);
            if (tid >= off) inc += v;
        }
        int run = inc - tot;
        #pragma unroll
        for (int ch = 0; ch < NCHUNK; ch++) { start[ch][tid] = run; run += cnt[ch][tid]; }
    }
    __syncthreads();
    int off = start[w][lane];
    int* pout = g_perm + b*LL;
    for (int t0 = 0; t0 < CHSZ; t0 += 128) {
        #pragma unroll
        for (int j = 0; j < 4; j++) buf[w][lane*4 + j] = lab[t0 + lane*4 + j];
        __syncwarp();
        #pragma unroll 8
        for (int e = 0; e < 128; e++) {
            if (buf[w][e] == lane) { pout[off] = w*CHSZ + t0 + e; off++; }
        }
        __syncwarp();
    }
}

// ---------------- conv3x3 reflect, 200->50, double-buffered, FFMA2 ----------------
__global__ __launch_bounds__(256) void conv_kernel(const float* __restrict__ input) {
    int tile = blockIdx.x, n = blockIdx.y;
    int l0 = tile * 64;
    int y = l0 >> 7, x0 = l0 & 127;
    __shared__ float inS[2][3*66];
    __shared__ float WxS[2][576];
    int tid = threadIdx.x, tx = tid & 15, ty = tid >> 4;
    ull acc2[4][2] = {{0ull,0ull},{0ull,0ull},{0ull,0ull},{0ull,0ull}};
    const float* inb = input + (size_t)n * CIN * LL;

    int in_off = -1;
    if (tid < 198) {
        int rr = tid / 66, cc = tid % 66;
        int gy = y - 1 + rr; gy = gy < 0 ? 1 : (gy > 127 ? 126 : gy);
        int gx = x0 - 1 + cc; gx = gx < 0 ? 1 : (gx > 127 ? 126 : gx);
        in_off = (gy << 7) + gx;
    }

    float wreg[3]; float ireg = 0.f;
    #pragma unroll
    for (int r = 0; r < 3; r++) { int e = tid + 256*r; if (e < 576) wreg[r] = g_WxT[e]; }
    if (in_off >= 0) ireg = inb[in_off];
    #pragma unroll
    for (int r = 0; r < 3; r++) { int e = tid + 256*r; if (e < 576) WxS[0][e] = wreg[r]; }
    if (in_off >= 0) inS[0][tid] = ireg;
    __syncthreads();

    for (int c = 0; c < CIN; ++c) {
        int p = c & 1;
        if (c + 1 < CIN) {
            #pragma unroll
            for (int r = 0; r < 3; r++) { int e = tid + 256*r; if (e < 576) wreg[r] = g_WxT[(c+1)*576 + e]; }
            if (in_off >= 0) ireg = inb[(size_t)(c+1)*LL + in_off];
        }
        const float* W = WxS[p];
        const float* I = inS[p];
        #pragma unroll
        for (int ky = 0; ky < 3; ky++)
        #pragma unroll
        for (int kx = 0; kx < 3; kx++) {
            ull w0, w1; ldq(&W[(ky*3 + kx)*64 + 4*tx], w0, w1);
            #pragma unroll
            for (int a = 0; a < 4; a++) {
                ull iv = dup2f(I[ky*66 + ty + 16*a + kx]);
                FMA2(acc2[a][0], iv, w0);
                FMA2(acc2[a][1], iv, w1);
            }
        }
        if (c + 1 < CIN) {
            #pragma unroll
            for (int r = 0; r < 3; r++) { int e = tid + 256*r; if (e < 576) WxS[p^1][e] = wreg[r]; }
            if (in_off >= 0) inS[p^1][tid] = ireg;
        }
        __syncthreads();
    }
    #pragma unroll
    for (int a = 0; a < 4; a++) {
        int l = l0 + ty + 16*a;
        size_t base = ((size_t)n*LL + l)*CQ + 4*tx;
        if (4*tx + 1 < CQ)
            *reinterpret_cast<float2*>(&g_xembed[base]) = upk2(acc2[a][0]);
        if (4*tx + 3 < CQ)
            *reinterpret_cast<float2*>(&g_xembed[base + 2]) = upk2(acc2[a][1]);
    }
}

// ---------------- 1x1 Wy GEMM, wide loads, FFMA2 ----------------
__global__ __launch_bounds__(256) void yembed_kernel(const float* __restrict__ input) {
    int tile = blockIdx.x, n = blockIdx.y;
    int l0 = tile * 64;
    __shared__ float inS[64*18];
    __shared__ float WyS[16*208];
    int tid = threadIdx.x, tx = tid & 31, ty8 = tid >> 5;
    ull acc2[13][2];
    #pragma unroll
    for (int pa = 0; pa < 13; pa++) { acc2[pa][0] = 0ull; acc2[pa][1] = 0ull; }
    const float* inb = input + (size_t)n * CIN * LL;
    for (int cb = 0; cb < 208; cb += 16) {
        __syncthreads();
        for (int e = tid; e < 16*64; e += 256) {
            int cc = e >> 6, li = e & 63;
            inS[li*18 + cc] = (cb + cc < CIN) ? inb[(size_t)(cb + cc)*LL + l0 + li] : 0.f;
        }
        for (int e = tid; e < 16*208; e += 256) {
            int cc = e / 208, o = e % 208;
            WyS[e] = (o < CIN && cb + cc < CIN) ? g_WyT[(cb + cc)*CIN + o] : 0.f;
        }
        __syncthreads();
        #pragma unroll
        for (int c2 = 0; c2 < 8; c2++) {
            float2 i0 = upk2(ldp(&inS[tx*18 + 2*c2]));
            float2 i1 = upk2(ldp(&inS[(tx + 32)*18 + 2*c2]));
            #pragma unroll
            for (int h = 0; h < 2; h++) {
                int cc = 2*c2 + h;
                ull d0 = dup2f(h ? i0.y : i0.x);
                ull d1 = dup2f(h ? i1.y : i1.x);
                #pragma unroll
                for (int q = 0; q < 6; q++) {
                    ull w0, w1; ldq(&WyS[cc*208 + 4*ty8 + 32*q], w0, w1);
                    FMA2(acc2[2*q][0], d0, w0);   FMA2(acc2[2*q][1], d1, w0);
                    FMA2(acc2[2*q+1][0], d0, w1); FMA2(acc2[2*q+1][1], d1, w1);
                }
                ull wt = ldp(&WyS[cc*208 + 192 + 2*ty8]);
                FMA2(acc2[12][0], d0, wt); FMA2(acc2[12][1], d1, wt);
            }
        }
    }
    float* yb0 = &g_yembed[((size_t)n*LL + l0 + tx)*CIN];
    float* yb1 = &g_yembed[((size_t)n*LL + l0 + tx + 32)*CIN];
    #pragma unroll
    for (int q = 0; q < 6; q++) {
        int o = 4*ty8 + 32*q;
        *reinterpret_cast<float4*>(&yb0[o]) = q2(acc2[2*q][0], acc2[2*q+1][0]);
        *reinterpret_cast<float4*>(&yb1[o]) = q2(acc2[2*q][1], acc2[2*q+1][1]);
    }
    if (ty8 < 4) {
        int o = 192 + 2*ty8;
        *reinterpret_cast<float2*>(&yb0[o]) = upk2(acc2[12][0]);
        *reinterpret_cast<float2*>(&yb1[o]) = upk2(acc2[12][1]);
    }
}

// ---------------- attention: 32-lane-distinct LDS tiling ----------------
// warp w owns rows 8w..8w+7; thread lane owns col-quads {4*lane} and a tail quad.
// dyn smem: P[64][196] | V: 2 x [32][208]; KsT[50][196]+Qs[64][52] alias the V region
__global__ __launch_bounds__(256, 2) void attn_kernel() {
    extern __shared__ float sm[];
    float* P   = sm;                  // 12544 fl
    float* Vs  = sm + 64*196;         // 2 x 6656 fl
    float* KsT = Vs;                  // 9800 fl
    float* Qs  = KsT + 50*196;        // 3328 fl
    __shared__ int lperm[192];
    int k = blockIdx.x, u = blockIdx.y, n = blockIdx.z;
    int tid = threadIdx.x;
    int lane = tid & 31, w = tid >> 5;
    int rbase = 8*w;

    const int* pbase = g_perm + (n*NSC + u)*LL;
    if (tid < 192) {
        int jj = tid & 63;
        int kk = tid < 64 ? k : (tid < 128 ? (k + KCL - 1) & (KCL - 1) : (k + 1) & (KCL - 1));
        lperm[tid] = pbase[kk*WIN + jj];
    }
    __syncthreads();

    const float* xb = g_xembed + (size_t)n*LL*CQ;
    for (int e = tid; e < 192*CQ; e += 256) {
        int j = e / CQ, c = e - j*CQ;
        KsT[c*196 + j] = xb[(size_t)lperm[j]*CQ + c];
    }
    for (int e = tid; e < 64*25; e += 256) {
        int i = e / 25, c2 = e - i*25;
        *reinterpret_cast<float2*>(&Qs[i*52 + 2*c2]) =
            *reinterpret_cast<const float2*>(&xb[(size_t)lperm[i]*CQ + 2*c2]);
    }
    __syncthreads();
    if (tid < 192) {
        float ss = 0.f;
        #pragma unroll 10
        for (int c = 0; c < CQ; c++) { float v = KsT[c*196 + tid]; ss += v*v; }
        float s = 1.f / fmaxf(sqrtf(ss), 5e-5f);
        #pragma unroll 10
        for (int c = 0; c < CQ; c++) KsT[c*196 + tid] *= s;
    }
    __syncthreads();

    // S = Q @ K^T  (rows 8w..8w+7, col quads 4*lane and 128+4*(lane&15))
    {
        int jc0 = 4*lane;
        int jc1 = 128 + 4*(lane & 15);
        ull accS[8][4];
        #pragma unroll
        for (int i = 0; i < 8; i++)
            #pragma unroll
            for (int t = 0; t < 4; t++) accS[i][t] = 0ull;
        #pragma unroll 2
        for (int c = 0; c < CQ; c++) {
            ull k0a, k0b, k1a, k1b;
            ldq(&KsT[c*196 + jc0], k0a, k0b);
            ldq(&KsT[c*196 + jc1], k1a, k1b);
            #pragma unroll
            for (int i = 0; i < 8; i++) {
                ull qd = dup2f(Qs[(rbase + i)*52 + c]);
                FMA2(accS[i][0], qd, k0a); FMA2(accS[i][1], qd, k0b);
                FMA2(accS[i][2], qd, k1a); FMA2(accS[i][3], qd, k1b);
            }
        }
        #pragma unroll
        for (int i = 0; i < 8; i++) {
            int r = rbase + i;
            *reinterpret_cast<float4*>(&P[r*196 + jc0]) = q2(accS[i][0], accS[i][1]);
            if (lane < 16)
                *reinterpret_cast<float4*>(&P[r*196 + jc1]) = q2(accS[i][2], accS[i][3]);
        }
    }
    __syncthreads();   // KsT/Qs dead after this point

    const float* yb = g_yembed + (size_t)n*LL*CIN;
    // issue async V loads for chunks 0,1 (overlap with softmax)
    #pragma unroll
    for (int c0 = 0; c0 < 2; c0++) {
        unsigned vb = s2u(Vs + c0*6656);
        for (int e = tid; e < 32*50; e += 256) {
            int row = e / 50, qd = e - row*50;
            cpa16(vb + (row*208 + 4*qd)*4,
                  yb + (size_t)lperm[c0*32 + row]*CIN + 4*qd);
        }
        CP_COMMIT();
    }
    // softmax over 192 cols
    {
        int r = tid >> 2, q = tid & 3;
        float* prow = P + r*196 + q*48;
        float mx = -1e30f;
        #pragma unroll 8
        for (int m = 0; m < 48; m++) mx = fmaxf(mx, prow[m]);
        mx = fmaxf(mx, __shfl_xor_sync(0xffffffffu, mx, 1));
        mx = fmaxf(mx, __shfl_xor_sync(0xffffffffu, mx, 2));
        float sum = 0.f;
        #pragma unroll 8
        for (int m = 0; m < 48; m++) { float e = __expf(prow[m] - mx); prow[m] = e; sum += e; }
        sum += __shfl_xor_sync(0xffffffffu, sum, 1);
        sum += __shfl_xor_sync(0xffffffffu, sum, 2);
        float inv = 1.f / sum;
        #pragma unroll 8
        for (int m = 0; m < 48; m++) prow[m] *= inv;
    }

    // O = P @ V; V 6 chunks of 32 rows, ping-pong; c quads 4*lane and tail
    int c0 = 4*lane;
    int c1 = 128 + 4*(lane < 18 ? lane : 0);
    ull accO[8][4];
    #pragma unroll
    for (int i = 0; i < 8; i++)
        #pragma unroll
        for (int t = 0; t < 4; t++) accO[i][t] = 0ull;
    for (int ch = 0; ch < 6; ch++) {
        if (ch < 5) CP_WAIT1(); else CP_WAIT0();
        __syncthreads();
        const float* V = Vs + (ch & 1)*6656;
        #pragma unroll 2
        for (int jj = 0; jj < 32; jj++) {
            int j = ch*32 + jj;
            ull v0a, v0b, v1a, v1b;
            ldq(&V[jj*208 + c0], v0a, v0b);
            ldq(&V[jj*208 + c1], v1a, v1b);
            #pragma unroll
            for (int i = 0; i < 8; i++) {
                ull pd = dup2f(P[(rbase + i)*196 + j]);
                FMA2(accO[i][0], pd, v0a); FMA2(accO[i][1], pd, v0b);
                FMA2(accO[i][2], pd, v1a); FMA2(accO[i][3], pd, v1b);
            }
        }
        __syncthreads();
        if (ch + 2 < 6) {
            unsigned vb = s2u(Vs + (ch & 1)*6656);
            for (int e = tid; e < 32*50; e += 256) {
                int row = e / 50, qd = e - row*50;
                cpa16(vb + (row*208 + 4*qd)*4,
                      yb + (size_t)lperm[(ch + 2)*32 + row]*CIN + 4*qd);
            }
            CP_COMMIT();
        }
    }
    float* ob = g_att + (size_t)(n*NSC + u)*LL*CIN;
    #pragma unroll
    for (int i = 0; i < 8; i++) {
        float* o = ob + (size_t)lperm[rbase + i]*CIN;
        *reinterpret_cast<float4*>(&o[c0]) = q2(accO[i][0], accO[i][1]);
        if (lane < 18)
            *reinterpret_cast<float4*>(&o[c1]) = q2(accO[i][2], accO[i][3]);
    }
}

// ---------------- Wout 1x1 (K=800) + bias + residual, cp.async double-buffered ----------------
__global__ __launch_bounds__(256) void out_kernel(const float* __restrict__ input,
                                                  const float* __restrict__ bout,
                                                  float* __restrict__ out) {
    extern __shared__ float osm[];
    float* attB = osm;                 // 2 x 2304 fl
    float* WoB  = osm + 2*2304;        // 2 x 6656 fl
    int tile = blockIdx.x, n = blockIdx.y;
    int l0 = tile * 64;
    int tid = threadIdx.x, tx = tid & 31, tyq = tid >> 5;
    ull acc2[13][2];
    #pragma unroll
    for (int pa = 0; pa < 13; pa++) { acc2[pa][0] = 0ull; acc2[pa][1] = 0ull; }

    auto issue = [&](int c, int bfr) {
        int k0 = c*32;
        unsigned ab = s2u(attB + bfr*2304);
        for (int e = tid; e < 512; e += 256) {
            int li = e >> 3, qd = e & 7;
            int kc = 4*qd, kk = k0 + kc;
            int u = kk / CIN, oc = kk - u*CIN;
            cpa16(ab + (li*36 + kc)*4,
                  g_att + ((size_t)(n*NSC + u)*LL + l0 + li)*CIN + oc);
        }
        unsigned wb = s2u(WoB + bfr*6656);
        for (int e = tid; e < 1600; e += 256) {
            int kc = e / 50, qd = e - kc*50;
            cpa16(wb + (kc*208 + 4*qd)*4,
                  g_WoutT + (size_t)(k0 + kc)*CIN + 4*qd);
        }
        CP_COMMIT();
    };

    issue(0, 0);
    issue(1, 1);
    for (int c = 0; c < 25; c++) {
        if (c < 24) CP_WAIT1(); else CP_WAIT0();
        __syncthreads();
        const float* aS = attB + (c & 1)*2304;
        const float* wS = WoB + (c & 1)*6656;
        #pragma unroll
        for (int k2 = 0; k2 < 16; k2++) {
            float2 a0 = upk2(ldp(&aS[tx*36 + 2*k2]));
            float2 a1 = upk2(ldp(&aS[(tx + 32)*36 + 2*k2]));
            #pragma unroll
            for (int h = 0; h < 2; h++) {
                ull d0 = dup2f(h ? a0.y : a0.x);
                ull d1 = dup2f(h ? a1.y : a1.x);
                int kc = 2*k2 + h;
                #pragma unroll
                for (int q = 0; q < 6; q++) {
                    ull w0, w1; ldq(&wS[kc*208 + 4*tyq + 32*q], w0, w1);
                    FMA2(acc2[2*q][0], d0, w0);   FMA2(acc2[2*q][1], d1, w0);
                    FMA2(acc2[2*q+1][0], d0, w1); FMA2(acc2[2*q+1][1], d1, w1);
                }
                if (tyq < 4) {
                    ull wt = ldp(&wS[kc*208 + 192 + 2*tyq]);
                    FMA2(acc2[12][0], d0, wt); FMA2(acc2[12][1], d1, wt);
                }
            }
        }
        __syncthreads();
        if (c + 2 < 25) issue(c + 2, c & 1);
    }
    #pragma unroll
    for (int pa = 0; pa < 13; pa++) {
        int co;
        if (pa < 12) co = 4*tyq + 32*(pa >> 1) + 2*(pa & 1);
        else { if (tyq >= 4) break; co = 192 + 2*tyq; }
        float b0 = bout[co], b1 = bout[co + 1];
        #pragma unroll
        for (int b = 0; b < 2; b++) {
            int l = l0 + tx + 32*b;
            size_t i0 = ((size_t)n*CIN + co)*LL + l;
            float2 v = upk2(acc2[pa][b]);
            out[i0]      = v.x + b0 + input[i0];
            out[i0 + LL] = v.y + b1 + input[i0 + LL];
        }
    }
}

// ---------------- launch ----------------
extern "C" void kernel_launch(void* const* d_in, const int* in_sizes, int n_in,
                              void* d_out, int out_size) {
    const float* input = (const float*)d_in[0];
    const int*   sem   = (const int*)d_in[1];
    const float* Wx    = (const float*)d_in[2];
    const float* Wy    = (const float*)d_in[3];
    const float* Wout  = (const float*)d_in[4];
    const float* bout  = (const float*)d_in[5];
    float* out = (float*)d_out;

    cudaFuncSetAttribute(attn_kernel, cudaFuncAttributeMaxDynamicSharedMemorySize, 103424);
    cudaFuncSetAttribute(out_kernel,  cudaFuncAttributeMaxDynamicSharedMemorySize, 71680);

    sortprep_kernel<<<dim3(NSC, NB), 256>>>(sem, Wx, Wy, Wout);
    conv_kernel<<<dim3(LL/64, NB), 256>>>(input);
    yembed_kernel<<<dim3(LL/64, NB), 256>>>(input);
    attn_kernel<<<dim3(KCL, NSC, NB), 256, 103424>>>();
    out_kernel<<<dim3(LL/64, NB), 256, 71680>>>(input, bout, out);
}